// round 4
// baseline (speedup 1.0000x reference)
#include <cuda_runtime.h>

#define Bn 256
#define Tn 512
#define Fn 128
#define Hn 256
#define BT (Bn*Tn)   // 131072
#define BH (Bn*Hn)   // 65536

// ---------------- scratch (device globals: sanctioned, no allocations) ----------------
__device__ float g_bufF1[(size_t)BT * Fn];     // 64 MB : xb, later ta_total
__device__ float g_bufF2[(size_t)BT * Fn];     // 64 MB : sa logits -> xs, later beta logits
__device__ float g_bufH1[(size_t)BT * Hn];     // 128 MB: h_in, later h1_all
__device__ float g_bufH2[(size_t)BT * Hn];     // 128 MB: h0_all
__device__ float g_bufG [(size_t)BT * 4 * Hn]; // 512 MB: gate preactivations (input side)
__device__ float g_hstate[2 * BH];             // ping-pong h
__device__ float g_ctxbuf[Bn * Fn];
__device__ unsigned g_bar;                     // grid-barrier counter (memset 0 before each persistent launch)

// ---------------- BatchNorm (eval) ----------------
__global__ void bn_kernel(const float4* __restrict__ x, const float4* __restrict__ g,
                          const float4* __restrict__ bt, const float4* __restrict__ mn,
                          const float4* __restrict__ vr, float4* __restrict__ out)
{
    int i = blockIdx.x * 256 + threadIdx.x;   // one float4 per thread, F=128 -> 32 float4 per row
    int fi = i & 31;
    float4 xv = x[i];
    float4 gv = g[fi], bv = bt[fi], mv = mn[fi], vv = vr[fi];
    float4 r;
    r.x = (xv.x - mv.x) * rsqrtf(vv.x + 1e-5f) * gv.x + bv.x;
    r.y = (xv.y - mv.y) * rsqrtf(vv.y + 1e-5f) * gv.y + bv.y;
    r.z = (xv.z - mv.z) * rsqrtf(vv.z + 1e-5f) * gv.z + bv.z;
    r.w = (xv.w - mv.w) * rsqrtf(vv.w + 1e-5f) * gv.w + bv.w;
    out[i] = r;
}

// ---------------- generic fp32 GEMM: C[M,N] = A[M,K] @ W[N,K]^T + bias, epilogue ----------------
// grid = (N/128, M/128), 256 threads, 128x128 block tile, 8x8 per thread, BK=16.
// epi: 0 none, 1 sigmoid, 2 relu
__global__ __launch_bounds__(256) void gemm_kernel(
    const float* __restrict__ A, const float* __restrict__ W,
    const float* __restrict__ b1, const float* __restrict__ b2,
    float* __restrict__ C, int N, int K, int epi)
{
    __shared__ float As[16][132];
    __shared__ float Ws[16][132];
    const int m0 = blockIdx.y << 7;
    const int n0 = blockIdx.x << 7;
    const int tid = threadIdx.x;
    const int tx = tid & 15;
    const int ty = tid >> 4;
    const int lr = tid >> 2;          // 0..63
    const int lk = (tid & 3) << 2;    // 0,4,8,12

    const float* Ap0 = A + (size_t)(m0 + lr) * K + lk;
    const float* Ap1 = A + (size_t)(m0 + lr + 64) * K + lk;
    const float* Wp0 = W + (size_t)(n0 + lr) * K + lk;
    const float* Wp1 = W + (size_t)(n0 + lr + 64) * K + lk;

    float acc[8][8];
#pragma unroll
    for (int i = 0; i < 8; i++)
#pragma unroll
        for (int j = 0; j < 8; j++) acc[i][j] = 0.f;

    for (int k0 = 0; k0 < K; k0 += 16) {
        float4 a0 = *(const float4*)(Ap0 + k0);
        float4 a1 = *(const float4*)(Ap1 + k0);
        float4 w0 = *(const float4*)(Wp0 + k0);
        float4 w1 = *(const float4*)(Wp1 + k0);
        As[lk+0][lr] = a0.x; As[lk+1][lr] = a0.y; As[lk+2][lr] = a0.z; As[lk+3][lr] = a0.w;
        As[lk+0][lr+64] = a1.x; As[lk+1][lr+64] = a1.y; As[lk+2][lr+64] = a1.z; As[lk+3][lr+64] = a1.w;
        Ws[lk+0][lr] = w0.x; Ws[lk+1][lr] = w0.y; Ws[lk+2][lr] = w0.z; Ws[lk+3][lr] = w0.w;
        Ws[lk+0][lr+64] = w1.x; Ws[lk+1][lr+64] = w1.y; Ws[lk+2][lr+64] = w1.z; Ws[lk+3][lr+64] = w1.w;
        __syncthreads();
#pragma unroll
        for (int kk = 0; kk < 16; kk++) {
            float a[8], w[8];
            *(float4*)&a[0] = *(const float4*)&As[kk][ty << 3];
            *(float4*)&a[4] = *(const float4*)&As[kk][(ty << 3) + 4];
            *(float4*)&w[0] = *(const float4*)&Ws[kk][tx << 3];
            *(float4*)&w[4] = *(const float4*)&Ws[kk][(tx << 3) + 4];
#pragma unroll
            for (int i = 0; i < 8; i++)
#pragma unroll
                for (int j = 0; j < 8; j++)
                    acc[i][j] = fmaf(a[i], w[j], acc[i][j]);
        }
        __syncthreads();
    }

    float bias[8];
#pragma unroll
    for (int j = 0; j < 8; j++) {
        int n = n0 + (tx << 3) + j;
        float bv = b1 ? b1[n] : 0.f;
        if (b2) bv += b2[n];
        bias[j] = bv;
    }
#pragma unroll
    for (int i = 0; i < 8; i++) {
        int m = m0 + (ty << 3) + i;
        float v[8];
#pragma unroll
        for (int j = 0; j < 8; j++) {
            float t = acc[i][j] + bias[j];
            if (epi == 1) t = 1.f / (1.f + expf(-t));
            else if (epi == 2) t = fmaxf(t, 0.f);
            v[j] = t;
        }
        float* cp = C + (size_t)m * N + n0 + (tx << 3);
        *(float4*)cp       = make_float4(v[0], v[1], v[2], v[3]);
        *(float4*)(cp + 4) = make_float4(v[4], v[5], v[6], v[7]);
    }
}

// ---------------- spatial-attention softmax + scale (in place on sx) ----------------
__global__ void sa_softmax_kernel(const float* __restrict__ xb, float* __restrict__ sx)
{
    int row = blockIdx.x;
    int f = threadIdx.x;
    size_t idx = ((size_t)row << 7) + f;
    float e = expf(sx[idx]);                 // logits in (0,1): exp is safe w/o max-shift
    float sum = e;
#pragma unroll
    for (int o = 16; o > 0; o >>= 1) sum += __shfl_xor_sync(0xffffffffu, sum, o);
    __shared__ float red[4];
    if ((f & 31) == 0) red[f >> 5] = sum;
    __syncthreads();
    float tot = red[0] + red[1] + red[2] + red[3];
    sx[idx] = xb[idx] * e / tot;
}

// ---------------- persistent LSTM layer: 512 fused recurrent steps in ONE kernel ----------------
// grid (16 u-tiles, 8 b-tiles) = 128 blocks (<=148 SMs, 1 block/SM by smem -> all co-resident),
// 128 threads. Whh tile (64 gate-cols x 256 k) cached in smem for the whole sequence; c-state
// lives in smem; cross-block sync via atomic counter + volatile spin (reset via memset node).
// G: input-side preactivations incl. biases, row (b*T+t), gate-major [i|f|g|o] x 256.
__global__ __launch_bounds__(128) void lstm_persist_kernel(
    const float* __restrict__ G, const float* __restrict__ Whh,
    float* __restrict__ hstate, float* __restrict__ hall, unsigned nb)
{
    extern __shared__ float sm[];
    float* ws  = sm;                    // [256][68]  W tile: ws[k*68 + c], c = gate*16+uu
    float* hsm = sm + 256 * 68;         // [256][36]  h tile: hsm[k*36 + bb]
    float* Ssm = hsm + 256 * 36;        // [32][68]   recurrent preact tile
    float* csm = Ssm + 32 * 68;         // [32][17]   c state

    const int u0 = blockIdx.x << 4;
    const int b0 = blockIdx.y << 5;
    const int tid = threadIdx.x;
    const int tx = tid & 15;            // cols tx*4..+3 (of 64)
    const int ty = tid >> 4;            // rows ty*4..+3 (of 32)

    // one-time: load W tile (4096 float4), zero c state
#pragma unroll 4
    for (int i = 0; i < 32; i++) {
        int f4 = tid + (i << 7);              // 0..4095
        int c  = f4 >> 6;                     // 0..63
        int kq = (f4 & 63) << 2;              // 0..252
        int wrow = ((c >> 4) << 8) + u0 + (c & 15);   // gate*256 + u
        float4 v = *(const float4*)(Whh + (size_t)wrow * Hn + kq);
        ws[(kq + 0) * 68 + c] = v.x;
        ws[(kq + 1) * 68 + c] = v.y;
        ws[(kq + 2) * 68 + c] = v.z;
        ws[(kq + 3) * 68 + c] = v.w;
    }
    for (int i = tid; i < 32 * 17; i += 128) csm[i] = 0.f;
    __syncthreads();

    unsigned target = 0;
    for (int t = 0; t < Tn; t++) {
        float acc[4][4];
#pragma unroll
        for (int i = 0; i < 4; i++)
#pragma unroll
            for (int j = 0; j < 4; j++) acc[i][j] = 0.f;

        if (t > 0) {
            // stage h_prev tile [32 x 256] (L1 bypass: other SMs wrote it last step)
            const float* hp = hstate + (t & 1) * BH;
#pragma unroll 4
            for (int i = 0; i < 16; i++) {
                int f4 = tid + (i << 7);          // 0..2047
                int bb = f4 >> 6;                 // 0..31
                int kq = (f4 & 63) << 2;
                float4 v = __ldcg((const float4*)(hp + (size_t)(b0 + bb) * Hn + kq));
                hsm[(kq + 0) * 36 + bb] = v.x;
                hsm[(kq + 1) * 36 + bb] = v.y;
                hsm[(kq + 2) * 36 + bb] = v.z;
                hsm[(kq + 3) * 36 + bb] = v.w;
            }
            __syncthreads();
#pragma unroll 8
            for (int kk = 0; kk < Hn; kk++) {
                float4 av = *(const float4*)&hsm[kk * 36 + (ty << 2)];
                float4 wv = *(const float4*)&ws[kk * 68 + (tx << 2)];
                float a[4] = {av.x, av.y, av.z, av.w};
                float w[4] = {wv.x, wv.y, wv.z, wv.w};
#pragma unroll
                for (int i = 0; i < 4; i++)
#pragma unroll
                    for (int j = 0; j < 4; j++)
                        acc[i][j] = fmaf(a[i], w[j], acc[i][j]);
            }
            __syncthreads();   // hsm/ws reads done before Ssm phase reuses nothing, but keeps phases clean
        }

        // deposit recurrent preactivations
#pragma unroll
        for (int i = 0; i < 4; i++)
#pragma unroll
            for (int j = 0; j < 4; j++)
                Ssm[((ty << 2) + i) * 68 + (tx << 2) + j] = acc[i][j];
        __syncthreads();

        // gate math: 512 cells (32 b x 16 u), 4 cells/thread
        float* hw = hstate + ((t + 1) & 1) * BH;
#pragma unroll
        for (int e = 0; e < 4; e++) {
            int cell = (tid << 2) + e;
            int uu = cell & 15;
            int bb = cell >> 4;
            int b = b0 + bb, u = u0 + uu;
            size_t gr = ((size_t)b * Tn + t) << 10;
            float gi = G[gr +   0 + u] + Ssm[bb * 68 +  0 + uu];
            float gf = G[gr + 256 + u] + Ssm[bb * 68 + 16 + uu];
            float gg = G[gr + 512 + u] + Ssm[bb * 68 + 32 + uu];
            float go = G[gr + 768 + u] + Ssm[bb * 68 + 48 + uu];
            float cprev = csm[bb * 17 + uu];
            float si = 1.f / (1.f + expf(-gi));
            float sf = 1.f / (1.f + expf(-gf));
            float so = 1.f / (1.f + expf(-go));
            float tg = tanhf(gg);
            float cn = sf * cprev + si * tg;
            float hv = so * tanhf(cn);
            csm[bb * 17 + uu] = cn;
            hw[(size_t)b * Hn + u] = hv;
            hall[((size_t)b * Tn + t) * Hn + u] = hv;
        }

        // grid barrier: h_t globally visible before any block starts step t+1
        __syncthreads();
        __threadfence();
        target += nb;
        if (tid == 0) {
            atomicAdd(&g_bar, 1u);
            while (*((volatile unsigned*)&g_bar) < target) { }
        }
        __syncthreads();
    }
}

// ---------------- temporal attention: softmax over T fused with weighted sum ----------------
__global__ void ctx_kernel(const float* __restrict__ blg, const float* __restrict__ tot,
                           float* __restrict__ ctx)
{
    int gid = blockIdx.x * 256 + threadIdx.x;   // 32768 = B*F
    int b = gid >> 7;
    int f = gid & 127;
    const float* lp = blg + (((size_t)b * Tn) << 7) + f;
    const float* tp = tot + (((size_t)b * Tn) << 7) + f;
    float m = -1e30f;
    for (int t = 0; t < Tn; t++) m = fmaxf(m, lp[(size_t)t << 7]);
    float s = 0.f, w = 0.f;
    for (int t = 0; t < Tn; t++) {
        float e = expf(lp[(size_t)t << 7] - m);
        s += e;
        w = fmaf(e, tp[(size_t)t << 7], w);
    }
    ctx[gid] = w / s;
}

// ---------------- final projection: out[b] = ctx[b,:] . out_W ----------------
__global__ void out_kernel(const float* __restrict__ ctx, const float* __restrict__ ow,
                           float* __restrict__ out)
{
    int b = blockIdx.x;
    int f = threadIdx.x;
    float v = ctx[(b << 7) + f] * ow[f];
#pragma unroll
    for (int o = 16; o > 0; o >>= 1) v += __shfl_xor_sync(0xffffffffu, v, o);
    __shared__ float red[4];
    if ((f & 31) == 0) red[f >> 5] = v;
    __syncthreads();
    if (f == 0) out[b] = red[0] + red[1] + red[2] + red[3];
}

// ---------------- host ----------------
extern "C" void kernel_launch(void* const* d_in, const int* in_sizes, int n_in,
                              void* d_out, int out_size)
{
    (void)in_sizes; (void)n_in; (void)out_size;
    const float* x    = (const float*)d_in[0];
    const float* bng  = (const float*)d_in[1];
    const float* bnb  = (const float*)d_in[2];
    const float* bnm  = (const float*)d_in[3];
    const float* bnv  = (const float*)d_in[4];
    const float* saW  = (const float*)d_in[5];
    const float* sab  = (const float*)d_in[6];
    const float* inW  = (const float*)d_in[7];
    const float* inb  = (const float*)d_in[8];
    const float* Wih0 = (const float*)d_in[9];
    const float* Whh0 = (const float*)d_in[10];
    const float* bih0 = (const float*)d_in[11];
    const float* bhh0 = (const float*)d_in[12];
    const float* Wih1 = (const float*)d_in[13];
    const float* Whh1 = (const float*)d_in[14];
    const float* bih1 = (const float*)d_in[15];
    const float* bhh1 = (const float*)d_in[16];
    const float* tahW = (const float*)d_in[17];
    const float* tahb = (const float*)d_in[18];
    const float* taW  = (const float*)d_in[19];
    const float* tab  = (const float*)d_in[20];
    const float* outW = (const float*)d_in[21];

    float *pF1, *pF2, *pH1, *pH2, *pG, *pHs, *pCtx;
    unsigned* pBar;
    cudaGetSymbolAddress((void**)&pF1, g_bufF1);
    cudaGetSymbolAddress((void**)&pF2, g_bufF2);
    cudaGetSymbolAddress((void**)&pH1, g_bufH1);
    cudaGetSymbolAddress((void**)&pH2, g_bufH2);
    cudaGetSymbolAddress((void**)&pG,  g_bufG);
    cudaGetSymbolAddress((void**)&pHs, g_hstate);
    cudaGetSymbolAddress((void**)&pCtx, g_ctxbuf);
    cudaGetSymbolAddress((void**)&pBar, g_bar);

    const int lstm_smem = (256 * 68 + 256 * 36 + 32 * 68 + 32 * 17) * 4;  // ~117 KB
    cudaFuncSetAttribute(lstm_persist_kernel,
                         cudaFuncAttributeMaxDynamicSharedMemorySize, lstm_smem);

    // 1) BN: xb -> F1
    bn_kernel<<<(BT * Fn / 4) / 256, 256>>>((const float4*)x, (const float4*)bng,
        (const float4*)bnb, (const float4*)bnm, (const float4*)bnv, (float4*)pF1);

    // 2) SA logits: sigmoid(xb @ saW^T + b) -> F2
    gemm_kernel<<<dim3(1, BT / 128), 256>>>(pF1, saW, sab, nullptr, pF2, Fn, Fn, 1);

    // 3) softmax over F + scale: F2 <- xb * softmax(F2)
    sa_softmax_kernel<<<BT, 128>>>(pF1, pF2);

    // 4) layer_in: h_in = xs @ inW^T + inb -> H1
    gemm_kernel<<<dim3(2, BT / 128), 256>>>(pF2, inW, inb, nullptr, pH1, Hn, Fn, 0);

    // 5) LSTM layer 0: batched input-side gates, then one persistent recurrent kernel
    gemm_kernel<<<dim3(8, BT / 128), 256>>>(pH1, Wih0, bih0, bhh0, pG, 4 * Hn, Hn, 0);
    cudaMemsetAsync(pBar, 0, sizeof(unsigned));
    lstm_persist_kernel<<<dim3(16, 8), 128, lstm_smem>>>(pG, Whh0, pHs, pH2, 128u);

    // 6) LSTM layer 1
    gemm_kernel<<<dim3(8, BT / 128), 256>>>(pH2, Wih1, bih1, bhh1, pG, 4 * Hn, Hn, 0);
    cudaMemsetAsync(pBar, 0, sizeof(unsigned));
    lstm_persist_kernel<<<dim3(16, 8), 128, lstm_smem>>>(pG, Whh1, pHs, pH1, 128u);

    // 7) temporal attention
    gemm_kernel<<<dim3(1, BT / 128), 256>>>(pH1, tahW, tahb, nullptr, pF1, Fn, Hn, 0); // total
    gemm_kernel<<<dim3(1, BT / 128), 256>>>(pF1, taW, tab, nullptr, pF2, Fn, Fn, 2);   // relu logits
    ctx_kernel<<<(Bn * Fn) / 256, 256>>>(pF2, pF1, pCtx);

    // 8) output
    out_kernel<<<Bn, 128>>>(pCtx, outW, (float*)d_out);
}

// round 5
// speedup vs baseline: 1.2947x; 1.2947x over previous
#include <cuda_runtime.h>

#define Bn 256
#define Tn 512
#define Fn 128
#define Hn 256
#define BT (Bn*Tn)   // 131072
#define BH (Bn*Hn)   // 65536

// ---------------- scratch (device globals: sanctioned, no allocations) ----------------
__device__ float g_bufF1[(size_t)BT * Fn];     // 64 MB : xb, later ta_total
__device__ float g_bufF2[(size_t)BT * Fn];     // 64 MB : sa logits -> xs, later beta logits
__device__ float g_bufH1[(size_t)BT * Hn];     // 128 MB: h_in, later h1_all
__device__ float g_bufH2[(size_t)BT * Hn];     // 128 MB: h0_all
__device__ float g_bufG [(size_t)BT * 4 * Hn]; // 512 MB: gate preactivations (input side)
__device__ float g_hstate[2 * BH];             // ping-pong h
__device__ float g_ctxbuf[Bn * Fn];
__device__ unsigned g_bar;                     // grid-barrier counter (memset 0 before each persistent launch)

// ---------------- BatchNorm (eval) ----------------
__global__ void bn_kernel(const float4* __restrict__ x, const float4* __restrict__ g,
                          const float4* __restrict__ bt, const float4* __restrict__ mn,
                          const float4* __restrict__ vr, float4* __restrict__ out)
{
    int i = blockIdx.x * 256 + threadIdx.x;
    int fi = i & 31;
    float4 xv = x[i];
    float4 gv = g[fi], bv = bt[fi], mv = mn[fi], vv = vr[fi];
    float4 r;
    r.x = (xv.x - mv.x) * rsqrtf(vv.x + 1e-5f) * gv.x + bv.x;
    r.y = (xv.y - mv.y) * rsqrtf(vv.y + 1e-5f) * gv.y + bv.y;
    r.z = (xv.z - mv.z) * rsqrtf(vv.z + 1e-5f) * gv.z + bv.z;
    r.w = (xv.w - mv.w) * rsqrtf(vv.w + 1e-5f) * gv.w + bv.w;
    out[i] = r;
}

// ---------------- generic fp32 GEMM: C[M,N] = A[M,K] @ W[N,K]^T + bias, epilogue ----------------
__global__ __launch_bounds__(256, 2) void gemm_kernel(
    const float* __restrict__ A, const float* __restrict__ W,
    const float* __restrict__ b1, const float* __restrict__ b2,
    float* __restrict__ C, int N, int K, int epi)
{
    __shared__ float As[16][132];
    __shared__ float Ws[16][132];
    const int m0 = blockIdx.y << 7;
    const int n0 = blockIdx.x << 7;
    const int tid = threadIdx.x;
    const int tx = tid & 15;
    const int ty = tid >> 4;
    const int lr = tid >> 2;          // 0..63
    const int lk = (tid & 3) << 2;    // 0,4,8,12

    const float* Ap0 = A + (size_t)(m0 + lr) * K + lk;
    const float* Ap1 = A + (size_t)(m0 + lr + 64) * K + lk;
    const float* Wp0 = W + (size_t)(n0 + lr) * K + lk;
    const float* Wp1 = W + (size_t)(n0 + lr + 64) * K + lk;

    float acc[8][8];
#pragma unroll
    for (int i = 0; i < 8; i++)
#pragma unroll
        for (int j = 0; j < 8; j++) acc[i][j] = 0.f;

    for (int k0 = 0; k0 < K; k0 += 16) {
        float4 a0 = *(const float4*)(Ap0 + k0);
        float4 a1 = *(const float4*)(Ap1 + k0);
        float4 w0 = *(const float4*)(Wp0 + k0);
        float4 w1 = *(const float4*)(Wp1 + k0);
        As[lk+0][lr] = a0.x; As[lk+1][lr] = a0.y; As[lk+2][lr] = a0.z; As[lk+3][lr] = a0.w;
        As[lk+0][lr+64] = a1.x; As[lk+1][lr+64] = a1.y; As[lk+2][lr+64] = a1.z; As[lk+3][lr+64] = a1.w;
        Ws[lk+0][lr] = w0.x; Ws[lk+1][lr] = w0.y; Ws[lk+2][lr] = w0.z; Ws[lk+3][lr] = w0.w;
        Ws[lk+0][lr+64] = w1.x; Ws[lk+1][lr+64] = w1.y; Ws[lk+2][lr+64] = w1.z; Ws[lk+3][lr+64] = w1.w;
        __syncthreads();
#pragma unroll
        for (int kk = 0; kk < 16; kk++) {
            float a[8], w[8];
            *(float4*)&a[0] = *(const float4*)&As[kk][ty << 3];
            *(float4*)&a[4] = *(const float4*)&As[kk][(ty << 3) + 4];
            *(float4*)&w[0] = *(const float4*)&Ws[kk][tx << 3];
            *(float4*)&w[4] = *(const float4*)&Ws[kk][(tx << 3) + 4];
#pragma unroll
            for (int i = 0; i < 8; i++)
#pragma unroll
                for (int j = 0; j < 8; j++)
                    acc[i][j] = fmaf(a[i], w[j], acc[i][j]);
        }
        __syncthreads();
    }

    float bias[8];
#pragma unroll
    for (int j = 0; j < 8; j++) {
        int n = n0 + (tx << 3) + j;
        float bv = b1 ? b1[n] : 0.f;
        if (b2) bv += b2[n];
        bias[j] = bv;
    }
#pragma unroll
    for (int i = 0; i < 8; i++) {
        int m = m0 + (ty << 3) + i;
        float v[8];
#pragma unroll
        for (int j = 0; j < 8; j++) {
            float t = acc[i][j] + bias[j];
            if (epi == 1) t = 1.f / (1.f + expf(-t));
            else if (epi == 2) t = fmaxf(t, 0.f);
            v[j] = t;
        }
        float* cp = C + (size_t)m * N + n0 + (tx << 3);
        *(float4*)cp       = make_float4(v[0], v[1], v[2], v[3]);
        *(float4*)(cp + 4) = make_float4(v[4], v[5], v[6], v[7]);
    }
}

// ---------------- spatial-attention softmax + scale (in place on sx) ----------------
__global__ void sa_softmax_kernel(const float* __restrict__ xb, float* __restrict__ sx)
{
    int row = blockIdx.x;
    int f = threadIdx.x;
    size_t idx = ((size_t)row << 7) + f;
    float e = expf(sx[idx]);                 // logits in (0,1): exp is safe w/o max-shift
    float sum = e;
#pragma unroll
    for (int o = 16; o > 0; o >>= 1) sum += __shfl_xor_sync(0xffffffffu, sum, o);
    __shared__ float red[4];
    if ((f & 31) == 0) red[f >> 5] = sum;
    __syncthreads();
    float tot = red[0] + red[1] + red[2] + red[3];
    sx[idx] = xb[idx] * e / tot;
}

// ---------------- persistent LSTM layer: 512 fused recurrent steps in ONE kernel ----------------
// grid (16 u-tiles, 8 b-tiles) = 128 blocks, 256 threads (8 warps). Split-K: warp-group
// grp = tid>>7 computes K half [grp*128, grp*128+128) into its own Ssm partial buffer;
// gate phase sums both. Whh tile + c-state resident in smem for all 512 steps. G gate
// preactivations prefetched into registers at step top (hides DRAM latency under GEMM).
// Cross-block sync: atomic counter + spin (reset via memset node before launch).
__global__ __launch_bounds__(256) void lstm_persist_kernel(
    const float* __restrict__ G, const float* __restrict__ Whh,
    float* __restrict__ hstate, float* __restrict__ hall, unsigned nb)
{
    extern __shared__ float sm[];
    float* ws  = sm;                    // [256][68]  W tile: ws[k*68 + c], c = gate*16+uu
    float* hsm = sm + 256 * 68;         // [256][36]  h tile: hsm[k*36 + bb]
    float* Ssm = hsm + 256 * 36;        // [2][32][68] recurrent preact partials
    float* csm = Ssm + 2 * 32 * 68;     // [32][18]   c state (even pad for float2)

    const int u0 = blockIdx.x << 4;
    const int b0 = blockIdx.y << 5;
    const int tid = threadIdx.x;
    const int grp = tid >> 7;           // K-group 0/1
    const int gt  = tid & 127;
    const int tx = gt & 15;             // cols tx*4..+3 (of 64)
    const int ty = gt >> 4;             // rows ty*4..+3 (of 32)

    // one-time: load W tile (4096 float4 over 256 threads), zero c state
#pragma unroll 4
    for (int i = 0; i < 16; i++) {
        int f4 = tid + (i << 8);              // 0..4095
        int c  = f4 >> 6;                     // 0..63
        int kq = (f4 & 63) << 2;              // 0..252
        int wrow = ((c >> 4) << 8) + u0 + (c & 15);   // gate*256 + u
        float4 v = *(const float4*)(Whh + (size_t)wrow * Hn + kq);
        ws[(kq + 0) * 68 + c] = v.x;
        ws[(kq + 1) * 68 + c] = v.y;
        ws[(kq + 2) * 68 + c] = v.z;
        ws[(kq + 3) * 68 + c] = v.w;
    }
    for (int i = tid; i < 32 * 18; i += 256) csm[i] = 0.f;
    __syncthreads();

    // gate-phase cell mapping: 2 consecutive cells per thread (same bb, uu even)
    const int uu = (tid << 1) & 15;
    const int bb = tid >> 3;
    const int gb = b0 + bb;
    const int gu = u0 + uu;

    unsigned target = 0;
    for (int t = 0; t < Tn; t++) {
        // prefetch this thread's gate preactivations (DRAM latency hidden under GEMM)
        float2 gqi, gqf, gqg, gqo;
        {
            const float* gp = G + (((size_t)gb * Tn + t) << 10) + gu;
            gqi = *(const float2*)(gp +   0);
            gqf = *(const float2*)(gp + 256);
            gqg = *(const float2*)(gp + 512);
            gqo = *(const float2*)(gp + 768);
        }

        float acc[4][4];
#pragma unroll
        for (int i = 0; i < 4; i++)
#pragma unroll
            for (int j = 0; j < 4; j++) acc[i][j] = 0.f;

        if (t > 0) {
            // stage h_prev tile [32 x 256] (L1 bypass: other SMs wrote it last step)
            const float* hp = hstate + (t & 1) * BH;
#pragma unroll 4
            for (int i = 0; i < 8; i++) {
                int f4 = tid + (i << 8);          // 0..2047
                int hbb = f4 >> 6;                // 0..31
                int kq = (f4 & 63) << 2;
                float4 v = __ldcg((const float4*)(hp + (size_t)(b0 + hbb) * Hn + kq));
                hsm[(kq + 0) * 36 + hbb] = v.x;
                hsm[(kq + 1) * 36 + hbb] = v.y;
                hsm[(kq + 2) * 36 + hbb] = v.z;
                hsm[(kq + 3) * 36 + hbb] = v.w;
            }
            __syncthreads();
            const float* hk = hsm + (grp << 7) * 36;
            const float* wk = ws  + (grp << 7) * 68;
#pragma unroll 8
            for (int kk = 0; kk < 128; kk++) {
                float4 av = *(const float4*)&hk[kk * 36 + (ty << 2)];
                float4 wv = *(const float4*)&wk[kk * 68 + (tx << 2)];
                float a[4] = {av.x, av.y, av.z, av.w};
                float w[4] = {wv.x, wv.y, wv.z, wv.w};
#pragma unroll
                for (int i = 0; i < 4; i++)
#pragma unroll
                    for (int j = 0; j < 4; j++)
                        acc[i][j] = fmaf(a[i], w[j], acc[i][j]);
            }
        }

        // deposit recurrent partials (per K-group)
        float* Sg = Ssm + grp * (32 * 68);
#pragma unroll
        for (int i = 0; i < 4; i++)
#pragma unroll
            for (int j = 0; j < 4; j++)
                Sg[((ty << 2) + i) * 68 + (tx << 2) + j] = acc[i][j];
        __syncthreads();

        // gate math: 512 cells, 2 per thread
        {
            const float* S0 = Ssm + bb * 68;
            const float* S1 = Ssm + 32 * 68 + bb * 68;
            float hv[2], cn[2];
            float2 cp = *(const float2*)&csm[bb * 18 + uu];
            float cprev[2] = {cp.x, cp.y};
            float gi2[2] = {gqi.x, gqi.y};
            float gf2[2] = {gqf.x, gqf.y};
            float gg2[2] = {gqg.x, gqg.y};
            float go2[2] = {gqo.x, gqo.y};
#pragma unroll
            for (int e = 0; e < 2; e++) {
                int ue = uu + e;
                float gi = gi2[e] + S0[ 0 + ue] + S1[ 0 + ue];
                float gf = gf2[e] + S0[16 + ue] + S1[16 + ue];
                float gg = gg2[e] + S0[32 + ue] + S1[32 + ue];
                float go = go2[e] + S0[48 + ue] + S1[48 + ue];
                float si = 1.f / (1.f + expf(-gi));
                float sf = 1.f / (1.f + expf(-gf));
                float so = 1.f / (1.f + expf(-go));
                float tg = tanhf(gg);
                cn[e] = sf * cprev[e] + si * tg;
                hv[e] = so * tanhf(cn[e]);
            }
            *(float2*)&csm[bb * 18 + uu] = make_float2(cn[0], cn[1]);
            float* hw = hstate + ((t + 1) & 1) * BH;
            *(float2*)(hw + (size_t)gb * Hn + gu) = make_float2(hv[0], hv[1]);
            *(float2*)(hall + ((size_t)gb * Tn + t) * Hn + gu) = make_float2(hv[0], hv[1]);
        }

        // grid barrier: h_t globally visible before any block starts step t+1
        __syncthreads();
        __threadfence();
        target += nb;
        if (tid == 0) {
            atomicAdd(&g_bar, 1u);
            while (*((volatile unsigned*)&g_bar) < target) { }
        }
        __syncthreads();
    }
}

// ---------------- temporal attention: softmax over T fused with weighted sum ----------------
__global__ void ctx_kernel(const float* __restrict__ blg, const float* __restrict__ tot,
                           float* __restrict__ ctx)
{
    int gid = blockIdx.x * 256 + threadIdx.x;   // 32768 = B*F
    int b = gid >> 7;
    int f = gid & 127;
    const float* lp = blg + (((size_t)b * Tn) << 7) + f;
    const float* tp = tot + (((size_t)b * Tn) << 7) + f;
    float m = -1e30f;
    for (int t = 0; t < Tn; t++) m = fmaxf(m, lp[(size_t)t << 7]);
    float s = 0.f, w = 0.f;
    for (int t = 0; t < Tn; t++) {
        float e = expf(lp[(size_t)t << 7] - m);
        s += e;
        w = fmaf(e, tp[(size_t)t << 7], w);
    }
    ctx[gid] = w / s;
}

// ---------------- final projection: out[b] = ctx[b,:] . out_W ----------------
__global__ void out_kernel(const float* __restrict__ ctx, const float* __restrict__ ow,
                           float* __restrict__ out)
{
    int b = blockIdx.x;
    int f = threadIdx.x;
    float v = ctx[(b << 7) + f] * ow[f];
#pragma unroll
    for (int o = 16; o > 0; o >>= 1) v += __shfl_xor_sync(0xffffffffu, v, o);
    __shared__ float red[4];
    if ((f & 31) == 0) red[f >> 5] = v;
    __syncthreads();
    if (f == 0) out[b] = red[0] + red[1] + red[2] + red[3];
}

// ---------------- host ----------------
extern "C" void kernel_launch(void* const* d_in, const int* in_sizes, int n_in,
                              void* d_out, int out_size)
{
    (void)in_sizes; (void)n_in; (void)out_size;
    const float* x    = (const float*)d_in[0];
    const float* bng  = (const float*)d_in[1];
    const float* bnb  = (const float*)d_in[2];
    const float* bnm  = (const float*)d_in[3];
    const float* bnv  = (const float*)d_in[4];
    const float* saW  = (const float*)d_in[5];
    const float* sab  = (const float*)d_in[6];
    const float* inW  = (const float*)d_in[7];
    const float* inb  = (const float*)d_in[8];
    const float* Wih0 = (const float*)d_in[9];
    const float* Whh0 = (const float*)d_in[10];
    const float* bih0 = (const float*)d_in[11];
    const float* bhh0 = (const float*)d_in[12];
    const float* Wih1 = (const float*)d_in[13];
    const float* Whh1 = (const float*)d_in[14];
    const float* bih1 = (const float*)d_in[15];
    const float* bhh1 = (const float*)d_in[16];
    const float* tahW = (const float*)d_in[17];
    const float* tahb = (const float*)d_in[18];
    const float* taW  = (const float*)d_in[19];
    const float* tab  = (const float*)d_in[20];
    const float* outW = (const float*)d_in[21];

    float *pF1, *pF2, *pH1, *pH2, *pG, *pHs, *pCtx;
    unsigned* pBar;
    cudaGetSymbolAddress((void**)&pF1, g_bufF1);
    cudaGetSymbolAddress((void**)&pF2, g_bufF2);
    cudaGetSymbolAddress((void**)&pH1, g_bufH1);
    cudaGetSymbolAddress((void**)&pH2, g_bufH2);
    cudaGetSymbolAddress((void**)&pG,  g_bufG);
    cudaGetSymbolAddress((void**)&pHs, g_hstate);
    cudaGetSymbolAddress((void**)&pCtx, g_ctxbuf);
    cudaGetSymbolAddress((void**)&pBar, g_bar);

    const int lstm_smem = (256 * 68 + 256 * 36 + 2 * 32 * 68 + 32 * 18) * 4;  // ~123 KB
    cudaFuncSetAttribute(lstm_persist_kernel,
                         cudaFuncAttributeMaxDynamicSharedMemorySize, lstm_smem);

    // 1) BN: xb -> F1
    bn_kernel<<<(BT * Fn / 4) / 256, 256>>>((const float4*)x, (const float4*)bng,
        (const float4*)bnb, (const float4*)bnm, (const float4*)bnv, (float4*)pF1);

    // 2) SA logits: sigmoid(xb @ saW^T + b) -> F2
    gemm_kernel<<<dim3(1, BT / 128), 256>>>(pF1, saW, sab, nullptr, pF2, Fn, Fn, 1);

    // 3) softmax over F + scale: F2 <- xb * softmax(F2)
    sa_softmax_kernel<<<BT, 128>>>(pF1, pF2);

    // 4) layer_in: h_in = xs @ inW^T + inb -> H1
    gemm_kernel<<<dim3(2, BT / 128), 256>>>(pF2, inW, inb, nullptr, pH1, Hn, Fn, 0);

    // 5) LSTM layer 0: batched input-side gates, then one persistent recurrent kernel
    gemm_kernel<<<dim3(8, BT / 128), 256>>>(pH1, Wih0, bih0, bhh0, pG, 4 * Hn, Hn, 0);
    cudaMemsetAsync(pBar, 0, sizeof(unsigned));
    lstm_persist_kernel<<<dim3(16, 8), 256, lstm_smem>>>(pG, Whh0, pHs, pH2, 128u);

    // 6) LSTM layer 1
    gemm_kernel<<<dim3(8, BT / 128), 256>>>(pH2, Wih1, bih1, bhh1, pG, 4 * Hn, Hn, 0);
    cudaMemsetAsync(pBar, 0, sizeof(unsigned));
    lstm_persist_kernel<<<dim3(16, 8), 256, lstm_smem>>>(pG, Whh1, pHs, pH1, 128u);

    // 7) temporal attention
    gemm_kernel<<<dim3(1, BT / 128), 256>>>(pH1, tahW, tahb, nullptr, pF1, Fn, Hn, 0); // total
    gemm_kernel<<<dim3(1, BT / 128), 256>>>(pF1, taW, tab, nullptr, pF2, Fn, Fn, 2);   // relu logits
    ctx_kernel<<<(Bn * Fn) / 256, 256>>>(pF2, pF1, pCtx);

    // 8) output
    out_kernel<<<Bn, 128>>>(pCtx, outW, (float*)d_out);
}

// round 7
// speedup vs baseline: 1.4592x; 1.1271x over previous
#include <cuda_runtime.h>
#include <cuda_bf16.h>
#include <cstdint>

#define Bn 256
#define Tn 512
#define Fn 128
#define Hn 256
#define BT (Bn*Tn)
#define BH (Bn*Hn)
#define SROW 72

// ---------------- scratch (device globals) ----------------
__device__ float g_bufF1[(size_t)BT * Fn];
__device__ float g_bufF2[(size_t)BT * Fn];
__device__ float g_bufH1[(size_t)BT * Hn];
__device__ float g_bufH2[(size_t)BT * Hn];
__device__ float g_bufG [(size_t)BT * 4 * Hn];
__device__ float g_hstate[2 * BH];
__device__ float g_ctxbuf[Bn * Fn];
__device__ unsigned g_bar;
__device__ __nv_bfloat16 g_a16h[(size_t)BT * Hn];
__device__ __nv_bfloat16 g_a16l[(size_t)BT * Hn];
__device__ __nv_bfloat16 g_w16h[4 * Hn * Hn];
__device__ __nv_bfloat16 g_w16l[4 * Hn * Hn];

// ---------------- BatchNorm (eval) ----------------
__global__ void bn_kernel(const float4* __restrict__ x, const float4* __restrict__ g,
                          const float4* __restrict__ bt, const float4* __restrict__ mn,
                          const float4* __restrict__ vr, float4* __restrict__ out)
{
    int i = blockIdx.x * 256 + threadIdx.x;
    int fi = i & 31;
    float4 xv = x[i];
    float4 gv = g[fi];
    float4 bv = bt[fi];
    float4 mv = mn[fi];
    float4 vv = vr[fi];
    float4 r;
    r.x = (xv.x - mv.x) * rsqrtf(vv.x + 1e-5f) * gv.x + bv.x;
    r.y = (xv.y - mv.y) * rsqrtf(vv.y + 1e-5f) * gv.y + bv.y;
    r.z = (xv.z - mv.z) * rsqrtf(vv.z + 1e-5f) * gv.z + bv.z;
    r.w = (xv.w - mv.w) * rsqrtf(vv.w + 1e-5f) * gv.w + bv.w;
    out[i] = r;
}

// ---------------- fp32 -> bf16 hi/lo split ----------------
__global__ void split_kernel(const float4* __restrict__ x,
                             __nv_bfloat162* __restrict__ hh,
                             __nv_bfloat162* __restrict__ ll)
{
    int i = blockIdx.x * 256 + threadIdx.x;
    float4 v = x[i];
    __nv_bfloat162 h0 = __floats2bfloat162_rn(v.x, v.y);
    __nv_bfloat162 h1 = __floats2bfloat162_rn(v.z, v.w);
    float lx = v.x - __bfloat162float(__low2bfloat16(h0));
    float ly = v.y - __bfloat162float(__high2bfloat16(h0));
    float lz = v.z - __bfloat162float(__low2bfloat16(h1));
    float lw = v.w - __bfloat162float(__high2bfloat16(h1));
    hh[2 * i]     = h0;
    hh[2 * i + 1] = h1;
    ll[2 * i]     = __floats2bfloat162_rn(lx, ly);
    ll[2 * i + 1] = __floats2bfloat162_rn(lz, lw);
}

// ---------------- tensor-core helpers ----------------
__device__ __forceinline__ void ldsm_x4(uint32_t* r, uint32_t saddr)
{
    asm volatile("ldmatrix.sync.aligned.m8n8.x4.shared.b16 {%0,%1,%2,%3}, [%4];"
                 : "=r"(r[0]), "=r"(r[1]), "=r"(r[2]), "=r"(r[3]) : "r"(saddr));
}

__device__ __forceinline__ void mma_bf16(float* d, const uint32_t* a, const uint32_t* b)
{
    asm volatile("mma.sync.aligned.m16n8k16.row.col.f32.bf16.bf16.f32 "
                 "{%0,%1,%2,%3}, {%4,%5,%6,%7}, {%8,%9}, {%0,%1,%2,%3};"
                 : "+f"(d[0]), "+f"(d[1]), "+f"(d[2]), "+f"(d[3])
                 : "r"(a[0]), "r"(a[1]), "r"(a[2]), "r"(a[3]), "r"(b[0]), "r"(b[1]));
}

// ---------------- bf16-split tensor GEMM: C[M,N] = A@W^T + bias, K=256 ----------------
// C = Ah*Wh + Ah*Wl + Al*Wh, fp32 accumulate. grid (N/128, M/128), 256 threads,
// 8 warps (2m x 4n), warp tile 64x32, K staged in 4 chunks of 64.
__global__ __launch_bounds__(256) void gemm_bf16_kernel(
    const __nv_bfloat16* __restrict__ Ahg, const __nv_bfloat16* __restrict__ Alg,
    const __nv_bfloat16* __restrict__ Whg, const __nv_bfloat16* __restrict__ Wlg,
    const float* __restrict__ b1, const float* __restrict__ b2,
    float* __restrict__ C, int N)
{
    extern __shared__ char dynsmem[];
    __nv_bfloat16* sAh = (__nv_bfloat16*)dynsmem;
    __nv_bfloat16* sAl = sAh + 128 * SROW;
    __nv_bfloat16* sWh = sAl + 128 * SROW;
    __nv_bfloat16* sWl = sWh + 128 * SROW;

    const int m0 = blockIdx.y << 7;
    const int n0 = blockIdx.x << 7;
    const int tid = (int)threadIdx.x;
    const int wid = tid >> 5;
    const int lane = tid & 31;
    const int wm0 = (wid >> 2) << 6;
    const int wn0 = (wid & 3) << 5;

    const int arow = (lane & 7) + (((lane >> 3) & 1) << 3);
    const int acol = (lane >> 4) << 3;
    const int brow = (lane & 7) + ((lane >> 4) << 3);
    const int bcol = ((lane >> 3) & 1) << 3;

    const uint32_t sAh0 = (uint32_t)__cvta_generic_to_shared(sAh) + (uint32_t)(((wm0 + arow) * SROW + acol) * 2);
    const uint32_t sAl0 = (uint32_t)__cvta_generic_to_shared(sAl) + (uint32_t)(((wm0 + arow) * SROW + acol) * 2);
    const uint32_t sWh0 = (uint32_t)__cvta_generic_to_shared(sWh) + (uint32_t)(((wn0 + brow) * SROW + bcol) * 2);
    const uint32_t sWl0 = (uint32_t)__cvta_generic_to_shared(sWl) + (uint32_t)(((wn0 + brow) * SROW + bcol) * 2);

    float acc[16][4];
#pragma unroll
    for (int i = 0; i < 16; i++) {
#pragma unroll
        for (int j = 0; j < 4; j++) { acc[i][j] = 0.f; }
    }

    const int lr = tid >> 1;
    const int lc = (tid & 1) << 5;      // 0 or 32: each thread stores 32 cols (4 x uint4)

    for (int kc = 0; kc < 4; kc++) {
        const __nv_bfloat16* ag = Ahg + (size_t)(m0 + lr) * 256 + kc * 64 + lc;
        const __nv_bfloat16* al = Alg + (size_t)(m0 + lr) * 256 + kc * 64 + lc;
        const __nv_bfloat16* wg = Whg + (size_t)(n0 + lr) * 256 + kc * 64 + lc;
        const __nv_bfloat16* wl = Wlg + (size_t)(n0 + lr) * 256 + kc * 64 + lc;
        __nv_bfloat16* dA_h = sAh + lr * SROW + lc;
        __nv_bfloat16* dA_l = sAl + lr * SROW + lc;
        __nv_bfloat16* dW_h = sWh + lr * SROW + lc;
        __nv_bfloat16* dW_l = sWl + lr * SROW + lc;
#pragma unroll
        for (int q = 0; q < 4; q++) {
            ((uint4*)(dA_h + q * 8))[0] = ((const uint4*)(ag + q * 8))[0];
            ((uint4*)(dA_l + q * 8))[0] = ((const uint4*)(al + q * 8))[0];
            ((uint4*)(dW_h + q * 8))[0] = ((const uint4*)(wg + q * 8))[0];
            ((uint4*)(dW_l + q * 8))[0] = ((const uint4*)(wl + q * 8))[0];
        }
        __syncthreads();

#pragma unroll
        for (int ks = 0; ks < 4; ks++) {
            const uint32_t koff = (uint32_t)(ks * 32);
            uint32_t afr[4][4];
            uint32_t bh[4][2];
            uint32_t bl[4][2];
#pragma unroll
            for (int fp = 0; fp < 2; fp++) {
                uint32_t tmp[4];
                ldsm_x4(tmp, sWh0 + (uint32_t)(fp * 16 * SROW * 2) + koff);
                bh[2 * fp][0] = tmp[0];
                bh[2 * fp][1] = tmp[1];
                bh[2 * fp + 1][0] = tmp[2];
                bh[2 * fp + 1][1] = tmp[3];
                ldsm_x4(tmp, sWl0 + (uint32_t)(fp * 16 * SROW * 2) + koff);
                bl[2 * fp][0] = tmp[0];
                bl[2 * fp][1] = tmp[1];
                bl[2 * fp + 1][0] = tmp[2];
                bl[2 * fp + 1][1] = tmp[3];
            }
#pragma unroll
            for (int fm = 0; fm < 4; fm++) {
                ldsm_x4(afr[fm], sAh0 + (uint32_t)(fm * 16 * SROW * 2) + koff);
            }
#pragma unroll
            for (int fm = 0; fm < 4; fm++) {
#pragma unroll
                for (int fn = 0; fn < 4; fn++) {
                    mma_bf16(acc[fm * 4 + fn], afr[fm], bh[fn]);
                    mma_bf16(acc[fm * 4 + fn], afr[fm], bl[fn]);
                }
            }
#pragma unroll
            for (int fm = 0; fm < 4; fm++) {
                ldsm_x4(afr[fm], sAl0 + (uint32_t)(fm * 16 * SROW * 2) + koff);
            }
#pragma unroll
            for (int fm = 0; fm < 4; fm++) {
#pragma unroll
                for (int fn = 0; fn < 4; fn++) {
                    mma_bf16(acc[fm * 4 + fn], afr[fm], bh[fn]);
                }
            }
        }
        __syncthreads();
    }

#pragma unroll
    for (int fm = 0; fm < 4; fm++) {
#pragma unroll
        for (int fn = 0; fn < 4; fn++) {
            float* d = acc[fm * 4 + fn];
            int row = m0 + wm0 + fm * 16 + (lane >> 2);
            int col = n0 + wn0 + fn * 8 + ((lane & 3) << 1);
            float bv0 = b1[col];
            float bv1 = b1[col + 1];
            if (b2 != nullptr) {
                bv0 += b2[col];
                bv1 += b2[col + 1];
            }
            float2 v0 = make_float2(d[0] + bv0, d[1] + bv1);
            float2 v1 = make_float2(d[2] + bv0, d[3] + bv1);
            ((float2*)(C + (size_t)row * N + col))[0] = v0;
            ((float2*)(C + (size_t)(row + 8) * N + col))[0] = v1;
        }
    }
}

// ---------------- generic fp32 GEMM (K=128 layers) ----------------
__global__ __launch_bounds__(256, 2) void gemm_kernel(
    const float* __restrict__ A, const float* __restrict__ W,
    const float* __restrict__ b1, const float* __restrict__ b2,
    float* __restrict__ C, int N, int K, int epi)
{
    __shared__ float As[16][132];
    __shared__ float Ws[16][132];
    const int m0 = blockIdx.y << 7;
    const int n0 = blockIdx.x << 7;
    const int tid = (int)threadIdx.x;
    const int tx = tid & 15;
    const int ty = tid >> 4;
    const int lr = tid >> 2;
    const int lk = (tid & 3) << 2;

    const float* Ap0 = A + (size_t)(m0 + lr) * K + lk;
    const float* Ap1 = A + (size_t)(m0 + lr + 64) * K + lk;
    const float* Wp0 = W + (size_t)(n0 + lr) * K + lk;
    const float* Wp1 = W + (size_t)(n0 + lr + 64) * K + lk;

    float acc[8][8];
#pragma unroll
    for (int i = 0; i < 8; i++) {
#pragma unroll
        for (int j = 0; j < 8; j++) { acc[i][j] = 0.f; }
    }

    for (int k0 = 0; k0 < K; k0 += 16) {
        float4 a0 = ((const float4*)(Ap0 + k0))[0];
        float4 a1 = ((const float4*)(Ap1 + k0))[0];
        float4 w0 = ((const float4*)(Wp0 + k0))[0];
        float4 w1 = ((const float4*)(Wp1 + k0))[0];
        As[lk+0][lr] = a0.x; As[lk+1][lr] = a0.y; As[lk+2][lr] = a0.z; As[lk+3][lr] = a0.w;
        As[lk+0][lr+64] = a1.x; As[lk+1][lr+64] = a1.y; As[lk+2][lr+64] = a1.z; As[lk+3][lr+64] = a1.w;
        Ws[lk+0][lr] = w0.x; Ws[lk+1][lr] = w0.y; Ws[lk+2][lr] = w0.z; Ws[lk+3][lr] = w0.w;
        Ws[lk+0][lr+64] = w1.x; Ws[lk+1][lr+64] = w1.y; Ws[lk+2][lr+64] = w1.z; Ws[lk+3][lr+64] = w1.w;
        __syncthreads();
#pragma unroll
        for (int kk = 0; kk < 16; kk++) {
            float a[8];
            float w[8];
            ((float4*)&a[0])[0] = ((const float4*)&As[kk][ty << 3])[0];
            ((float4*)&a[4])[0] = ((const float4*)&As[kk][(ty << 3) + 4])[0];
            ((float4*)&w[0])[0] = ((const float4*)&Ws[kk][tx << 3])[0];
            ((float4*)&w[4])[0] = ((const float4*)&Ws[kk][(tx << 3) + 4])[0];
#pragma unroll
            for (int i = 0; i < 8; i++) {
#pragma unroll
                for (int j = 0; j < 8; j++) {
                    acc[i][j] = fmaf(a[i], w[j], acc[i][j]);
                }
            }
        }
        __syncthreads();
    }

    float bias[8];
#pragma unroll
    for (int j = 0; j < 8; j++) {
        int n = n0 + (tx << 3) + j;
        float bv = (b1 != nullptr) ? b1[n] : 0.f;
        if (b2 != nullptr) { bv += b2[n]; }
        bias[j] = bv;
    }
#pragma unroll
    for (int i = 0; i < 8; i++) {
        int m = m0 + (ty << 3) + i;
        float v[8];
#pragma unroll
        for (int j = 0; j < 8; j++) {
            float t = acc[i][j] + bias[j];
            if (epi == 1) { t = 1.f / (1.f + expf(-t)); }
            else if (epi == 2) { t = fmaxf(t, 0.f); }
            v[j] = t;
        }
        float* cp = C + (size_t)m * N + n0 + (tx << 3);
        ((float4*)cp)[0]       = make_float4(v[0], v[1], v[2], v[3]);
        ((float4*)(cp + 4))[0] = make_float4(v[4], v[5], v[6], v[7]);
    }
}

// ---------------- spatial-attention softmax + scale ----------------
__global__ void sa_softmax_kernel(const float* __restrict__ xb, float* __restrict__ sx)
{
    int row = blockIdx.x;
    int f = threadIdx.x;
    size_t idx = ((size_t)row << 7) + f;
    float e = expf(sx[idx]);
    float sum = e;
#pragma unroll
    for (int o = 16; o > 0; o >>= 1) { sum += __shfl_xor_sync(0xffffffffu, sum, o); }
    __shared__ float red[4];
    if ((f & 31) == 0) { red[f >> 5] = sum; }
    __syncthreads();
    float tot = red[0] + red[1] + red[2] + red[3];
    sx[idx] = xb[idx] * e / tot;
}

// ---------------- persistent LSTM layer ----------------
__global__ __launch_bounds__(256) void lstm_persist_kernel(
    const float* __restrict__ G, const float* __restrict__ Whh,
    float* __restrict__ hstate, float* __restrict__ hall, unsigned nb)
{
    extern __shared__ char dynsmem[];
    float* ws  = (float*)dynsmem;       // [256][68]
    float* hsm = ws + 256 * 68;         // [256][36]
    float* Ssm = hsm + 256 * 36;        // [2][32][68]
    float* csm = Ssm + 2 * 32 * 68;     // [32][18]

    const int u0 = blockIdx.x << 4;
    const int b0 = blockIdx.y << 5;
    const int tid = (int)threadIdx.x;
    const int grp = tid >> 7;
    const int gt  = tid & 127;
    const int tx = gt & 15;
    const int ty = gt >> 4;

#pragma unroll 4
    for (int i = 0; i < 16; i++) {
        int f4 = tid + (i << 8);
        int c  = f4 >> 6;
        int kq = (f4 & 63) << 2;
        int wrow = ((c >> 4) << 8) + u0 + (c & 15);
        float4 v = ((const float4*)(Whh + (size_t)wrow * Hn + kq))[0];
        ws[(kq + 0) * 68 + c] = v.x;
        ws[(kq + 1) * 68 + c] = v.y;
        ws[(kq + 2) * 68 + c] = v.z;
        ws[(kq + 3) * 68 + c] = v.w;
    }
    for (int i = tid; i < 32 * 18; i += 256) { csm[i] = 0.f; }
    __syncthreads();

    const int uu = (tid << 1) & 15;
    const int bb = tid >> 3;
    const int gb = b0 + bb;
    const int gu = u0 + uu;

    unsigned target = 0;
    for (int t = 0; t < Tn; t++) {
        float2 gqi, gqf, gqg, gqo;
        {
            const float* gp = G + (((size_t)gb * Tn + t) << 10) + gu;
            gqi = ((const float2*)(gp +   0))[0];
            gqf = ((const float2*)(gp + 256))[0];
            gqg = ((const float2*)(gp + 512))[0];
            gqo = ((const float2*)(gp + 768))[0];
        }

        float acc[4][4];
#pragma unroll
        for (int i = 0; i < 4; i++) {
#pragma unroll
            for (int j = 0; j < 4; j++) { acc[i][j] = 0.f; }
        }

        if (t > 0) {
            const float* hp = hstate + (t & 1) * BH;
#pragma unroll 4
            for (int i = 0; i < 8; i++) {
                int f4 = tid + (i << 8);
                int hbb = f4 >> 6;
                int kq = (f4 & 63) << 2;
                float4 v = __ldcg((const float4*)(hp + (size_t)(b0 + hbb) * Hn + kq));
                hsm[(kq + 0) * 36 + hbb] = v.x;
                hsm[(kq + 1) * 36 + hbb] = v.y;
                hsm[(kq + 2) * 36 + hbb] = v.z;
                hsm[(kq + 3) * 36 + hbb] = v.w;
            }
            __syncthreads();
            const float* hk = hsm + (grp << 7) * 36;
            const float* wk = ws  + (grp << 7) * 68;
#pragma unroll 8
            for (int kk = 0; kk < 128; kk++) {
                float4 av = ((const float4*)&hk[kk * 36 + (ty << 2)])[0];
                float4 wv = ((const float4*)&wk[kk * 68 + (tx << 2)])[0];
                float a0 = av.x, a1 = av.y, a2 = av.z, a3 = av.w;
                float w0 = wv.x, w1 = wv.y, w2 = wv.z, w3 = wv.w;
                acc[0][0] = fmaf(a0, w0, acc[0][0]); acc[0][1] = fmaf(a0, w1, acc[0][1]);
                acc[0][2] = fmaf(a0, w2, acc[0][2]); acc[0][3] = fmaf(a0, w3, acc[0][3]);
                acc[1][0] = fmaf(a1, w0, acc[1][0]); acc[1][1] = fmaf(a1, w1, acc[1][1]);
                acc[1][2] = fmaf(a1, w2, acc[1][2]); acc[1][3] = fmaf(a1, w3, acc[1][3]);
                acc[2][0] = fmaf(a2, w0, acc[2][0]); acc[2][1] = fmaf(a2, w1, acc[2][1]);
                acc[2][2] = fmaf(a2, w2, acc[2][2]); acc[2][3] = fmaf(a2, w3, acc[2][3]);
                acc[3][0] = fmaf(a3, w0, acc[3][0]); acc[3][1] = fmaf(a3, w1, acc[3][1]);
                acc[3][2] = fmaf(a3, w2, acc[3][2]); acc[3][3] = fmaf(a3, w3, acc[3][3]);
            }
        }

        float* Sg = Ssm + grp * (32 * 68);
#pragma unroll
        for (int i = 0; i < 4; i++) {
#pragma unroll
            for (int j = 0; j < 4; j++) {
                Sg[((ty << 2) + i) * 68 + (tx << 2) + j] = acc[i][j];
            }
        }
        __syncthreads();

        {
            const float* S0 = Ssm + bb * 68;
            const float* S1 = Ssm + 32 * 68 + bb * 68;
            float hv[2];
            float cn[2];
            float2 cpv = ((const float2*)&csm[bb * 18 + uu])[0];
            float cprev[2] = {cpv.x, cpv.y};
            float gi2[2] = {gqi.x, gqi.y};
            float gf2[2] = {gqf.x, gqf.y};
            float gg2[2] = {gqg.x, gqg.y};
            float go2[2] = {gqo.x, gqo.y};
#pragma unroll
            for (int e = 0; e < 2; e++) {
                int ue = uu + e;
                float gi = gi2[e] + S0[ 0 + ue] + S1[ 0 + ue];
                float gf = gf2[e] + S0[16 + ue] + S1[16 + ue];
                float gg = gg2[e] + S0[32 + ue] + S1[32 + ue];
                float go = go2[e] + S0[48 + ue] + S1[48 + ue];
                float si = 1.f / (1.f + expf(-gi));
                float sf = 1.f / (1.f + expf(-gf));
                float so = 1.f / (1.f + expf(-go));
                float tg = tanhf(gg);
                cn[e] = sf * cprev[e] + si * tg;
                hv[e] = so * tanhf(cn[e]);
            }
            ((float2*)&csm[bb * 18 + uu])[0] = make_float2(cn[0], cn[1]);
            float* hw = hstate + ((t + 1) & 1) * BH;
            ((float2*)(hw + (size_t)gb * Hn + gu))[0] = make_float2(hv[0], hv[1]);
            ((float2*)(hall + ((size_t)gb * Tn + t) * Hn + gu))[0] = make_float2(hv[0], hv[1]);
        }

        __syncthreads();
        __threadfence();
        target += nb;
        if (tid == 0) {
            atomicAdd(&g_bar, 1u);
            while (*((volatile unsigned*)&g_bar) < target) { }
        }
        __syncthreads();
    }
}

// ---------------- temporal attention ----------------
__global__ void ctx_kernel(const float* __restrict__ blg, const float* __restrict__ tot,
                           float* __restrict__ ctx)
{
    int gid = blockIdx.x * 256 + threadIdx.x;
    int b = gid >> 7;
    int f = gid & 127;
    const float* lp = blg + (((size_t)b * Tn) << 7) + f;
    const float* tp = tot + (((size_t)b * Tn) << 7) + f;
    float m = -1e30f;
    for (int t = 0; t < Tn; t++) { m = fmaxf(m, lp[(size_t)t << 7]); }
    float s = 0.f;
    float w = 0.f;
    for (int t = 0; t < Tn; t++) {
        float e = expf(lp[(size_t)t << 7] - m);
        s += e;
        w = fmaf(e, tp[(size_t)t << 7], w);
    }
    ctx[gid] = w / s;
}

// ---------------- final projection ----------------
__global__ void out_kernel(const float* __restrict__ ctx, const float* __restrict__ ow,
                           float* __restrict__ out)
{
    int b = blockIdx.x;
    int f = threadIdx.x;
    float v = ctx[(b << 7) + f] * ow[f];
#pragma unroll
    for (int o = 16; o > 0; o >>= 1) { v += __shfl_xor_sync(0xffffffffu, v, o); }
    __shared__ float red[4];
    if ((f & 31) == 0) { red[f >> 5] = v; }
    __syncthreads();
    if (f == 0) { out[b] = red[0] + red[1] + red[2] + red[3]; }
}

// ---------------- host ----------------
extern "C" void kernel_launch(void* const* d_in, const int* in_sizes, int n_in,
                              void* d_out, int out_size)
{
    (void)in_sizes; (void)n_in; (void)out_size;
    const float* x    = (const float*)d_in[0];
    const float* bng  = (const float*)d_in[1];
    const float* bnb  = (const float*)d_in[2];
    const float* bnm  = (const float*)d_in[3];
    const float* bnv  = (const float*)d_in[4];
    const float* saW  = (const float*)d_in[5];
    const float* sab  = (const float*)d_in[6];
    const float* inW  = (const float*)d_in[7];
    const float* inb  = (const float*)d_in[8];
    const float* Wih0 = (const float*)d_in[9];
    const float* Whh0 = (const float*)d_in[10];
    const float* bih0 = (const float*)d_in[11];
    const float* bhh0 = (const float*)d_in[12];
    const float* Wih1 = (const float*)d_in[13];
    const float* Whh1 = (const float*)d_in[14];
    const float* bih1 = (const float*)d_in[15];
    const float* bhh1 = (const float*)d_in[16];
    const float* tahW = (const float*)d_in[17];
    const float* tahb = (const float*)d_in[18];
    const float* taW  = (const float*)d_in[19];
    const float* tab  = (const float*)d_in[20];
    const float* outW = (const float*)d_in[21];

    float *pF1, *pF2, *pH1, *pH2, *pG, *pHs, *pCtx;
    unsigned* pBar;
    __nv_bfloat16 *pAh, *pAl, *pWh, *pWl;
    cudaGetSymbolAddress((void**)&pF1, g_bufF1);
    cudaGetSymbolAddress((void**)&pF2, g_bufF2);
    cudaGetSymbolAddress((void**)&pH1, g_bufH1);
    cudaGetSymbolAddress((void**)&pH2, g_bufH2);
    cudaGetSymbolAddress((void**)&pG,  g_bufG);
    cudaGetSymbolAddress((void**)&pHs, g_hstate);
    cudaGetSymbolAddress((void**)&pCtx, g_ctxbuf);
    cudaGetSymbolAddress((void**)&pBar, g_bar);
    cudaGetSymbolAddress((void**)&pAh, g_a16h);
    cudaGetSymbolAddress((void**)&pAl, g_a16l);
    cudaGetSymbolAddress((void**)&pWh, g_w16h);
    cudaGetSymbolAddress((void**)&pWl, g_w16l);

    const int lstm_smem = (256 * 68 + 256 * 36 + 2 * 32 * 68 + 32 * 18) * 4;
    cudaFuncSetAttribute(lstm_persist_kernel,
                         cudaFuncAttributeMaxDynamicSharedMemorySize, lstm_smem);
    const int bf16_smem = 4 * 128 * SROW * 2;
    cudaFuncSetAttribute(gemm_bf16_kernel,
                         cudaFuncAttributeMaxDynamicSharedMemorySize, bf16_smem);

    const int SPLIT_A_BLKS = (BT * Hn / 4) / 256;
    const int SPLIT_W_BLKS = (4 * Hn * Hn / 4) / 256;
    const int SPLIT_T_BLKS = (Fn * Hn / 4) / 256;

    // 1) BN
    bn_kernel<<<(BT * Fn / 4) / 256, 256>>>((const float4*)x, (const float4*)bng,
        (const float4*)bnb, (const float4*)bnm, (const float4*)bnv, (float4*)pF1);

    // 2) SA logits
    gemm_kernel<<<dim3(1, BT / 128), 256>>>(pF1, saW, sab, nullptr, pF2, Fn, Fn, 1);

    // 3) softmax + scale
    sa_softmax_kernel<<<BT, 128>>>(pF1, pF2);

    // 4) layer_in
    gemm_kernel<<<dim3(2, BT / 128), 256>>>(pF2, inW, inb, nullptr, pH1, Hn, Fn, 0);

    // 5) LSTM layer 0
    split_kernel<<<SPLIT_A_BLKS, 256>>>((const float4*)pH1, (__nv_bfloat162*)pAh, (__nv_bfloat162*)pAl);
    split_kernel<<<SPLIT_W_BLKS, 256>>>((const float4*)Wih0, (__nv_bfloat162*)pWh, (__nv_bfloat162*)pWl);
    gemm_bf16_kernel<<<dim3(8, BT / 128), 256, bf16_smem>>>(pAh, pAl, pWh, pWl, bih0, bhh0, pG, 4 * Hn);
    cudaMemsetAsync(pBar, 0, sizeof(unsigned));
    lstm_persist_kernel<<<dim3(16, 8), 256, lstm_smem>>>(pG, Whh0, pHs, pH2, 128u);

    // 6) LSTM layer 1
    split_kernel<<<SPLIT_A_BLKS, 256>>>((const float4*)pH2, (__nv_bfloat162*)pAh, (__nv_bfloat162*)pAl);
    split_kernel<<<SPLIT_W_BLKS, 256>>>((const float4*)Wih1, (__nv_bfloat162*)pWh, (__nv_bfloat162*)pWl);
    gemm_bf16_kernel<<<dim3(8, BT / 128), 256, bf16_smem>>>(pAh, pAl, pWh, pWl, bih1, bhh1, pG, 4 * Hn);
    cudaMemsetAsync(pBar, 0, sizeof(unsigned));
    lstm_persist_kernel<<<dim3(16, 8), 256, lstm_smem>>>(pG, Whh1, pHs, pH1, 128u);

    // 7) temporal attention
    split_kernel<<<SPLIT_A_BLKS, 256>>>((const float4*)pH1, (__nv_bfloat162*)pAh, (__nv_bfloat162*)pAl);
    split_kernel<<<SPLIT_T_BLKS, 256>>>((const float4*)tahW, (__nv_bfloat162*)pWh, (__nv_bfloat162*)pWl);
    gemm_bf16_kernel<<<dim3(1, BT / 128), 256, bf16_smem>>>(pAh, pAl, pWh, pWl, tahb, nullptr, pF1, Fn);
    gemm_kernel<<<dim3(1, BT / 128), 256>>>(pF1, taW, tab, nullptr, pF2, Fn, Fn, 2);
    ctx_kernel<<<(Bn * Fn) / 256, 256>>>(pF2, pF1, pCtx);

    // 8) output
    out_kernel<<<Bn, 128>>>(pCtx, outW, (float*)d_out);
}

// round 8
// speedup vs baseline: 2.3551x; 1.6139x over previous
#include <cuda_runtime.h>
#include <cuda_bf16.h>
#include <cstdint>

#define Bn 256
#define Tn 512
#define Fn 128
#define Hn 256
#define BT (Bn*Tn)
#define BH (Bn*Hn)
#define SROW 72
#define SROWK 264   // LSTM smem row stride (256 k + 8 pad), 528B: 16B-aligned, LDSM conflict-free

// ---------------- scratch (device globals) ----------------
__device__ float g_bufF1[(size_t)BT * Fn];
__device__ float g_bufF2[(size_t)BT * Fn];
__device__ float g_bufH1[(size_t)BT * Hn];
__device__ float g_bufH2[(size_t)BT * Hn];
__device__ float g_bufG [(size_t)BT * 4 * Hn];
__device__ float g_ctxbuf[Bn * Fn];
__device__ unsigned g_bar;
__device__ __nv_bfloat16 g_a16h[(size_t)BT * Hn];
__device__ __nv_bfloat16 g_a16l[(size_t)BT * Hn];
__device__ __nv_bfloat16 g_w16h[4 * Hn * Hn];
__device__ __nv_bfloat16 g_w16l[4 * Hn * Hn];
__device__ __nv_bfloat16 g_h16h[2 * BH];   // ping-pong h (bf16 hi)
__device__ __nv_bfloat16 g_h16l[2 * BH];   // ping-pong h (bf16 lo)

// ---------------- BatchNorm (eval) ----------------
__global__ void bn_kernel(const float4* __restrict__ x, const float4* __restrict__ g,
                          const float4* __restrict__ bt, const float4* __restrict__ mn,
                          const float4* __restrict__ vr, float4* __restrict__ out)
{
    int i = blockIdx.x * 256 + threadIdx.x;
    int fi = i & 31;
    float4 xv = x[i];
    float4 gv = g[fi];
    float4 bv = bt[fi];
    float4 mv = mn[fi];
    float4 vv = vr[fi];
    float4 r;
    r.x = (xv.x - mv.x) * rsqrtf(vv.x + 1e-5f) * gv.x + bv.x;
    r.y = (xv.y - mv.y) * rsqrtf(vv.y + 1e-5f) * gv.y + bv.y;
    r.z = (xv.z - mv.z) * rsqrtf(vv.z + 1e-5f) * gv.z + bv.z;
    r.w = (xv.w - mv.w) * rsqrtf(vv.w + 1e-5f) * gv.w + bv.w;
    out[i] = r;
}

// ---------------- fp32 -> bf16 hi/lo split ----------------
__global__ void split_kernel(const float4* __restrict__ x,
                             __nv_bfloat162* __restrict__ hh,
                             __nv_bfloat162* __restrict__ ll)
{
    int i = blockIdx.x * 256 + threadIdx.x;
    float4 v = x[i];
    __nv_bfloat162 h0 = __floats2bfloat162_rn(v.x, v.y);
    __nv_bfloat162 h1 = __floats2bfloat162_rn(v.z, v.w);
    float lx = v.x - __bfloat162float(__low2bfloat16(h0));
    float ly = v.y - __bfloat162float(__high2bfloat16(h0));
    float lz = v.z - __bfloat162float(__low2bfloat16(h1));
    float lw = v.w - __bfloat162float(__high2bfloat16(h1));
    hh[2 * i]     = h0;
    hh[2 * i + 1] = h1;
    ll[2 * i]     = __floats2bfloat162_rn(lx, ly);
    ll[2 * i + 1] = __floats2bfloat162_rn(lz, lw);
}

// ---------------- tensor-core helpers ----------------
__device__ __forceinline__ void ldsm_x4(uint32_t* r, uint32_t saddr)
{
    asm volatile("ldmatrix.sync.aligned.m8n8.x4.shared.b16 {%0,%1,%2,%3}, [%4];"
                 : "=r"(r[0]), "=r"(r[1]), "=r"(r[2]), "=r"(r[3]) : "r"(saddr));
}

__device__ __forceinline__ void ldsm_x2(uint32_t* r, uint32_t saddr)
{
    asm volatile("ldmatrix.sync.aligned.m8n8.x2.shared.b16 {%0,%1}, [%2];"
                 : "=r"(r[0]), "=r"(r[1]) : "r"(saddr));
}

__device__ __forceinline__ void mma_bf16(float* d, const uint32_t* a, const uint32_t* b)
{
    asm volatile("mma.sync.aligned.m16n8k16.row.col.f32.bf16.bf16.f32 "
                 "{%0,%1,%2,%3}, {%4,%5,%6,%7}, {%8,%9}, {%0,%1,%2,%3};"
                 : "+f"(d[0]), "+f"(d[1]), "+f"(d[2]), "+f"(d[3])
                 : "r"(a[0]), "r"(a[1]), "r"(a[2]), "r"(a[3]), "r"(b[0]), "r"(b[1]));
}

// ---------------- bf16-split tensor GEMM: C[M,N] = A@W^T + bias, K=256 ----------------
__global__ __launch_bounds__(256) void gemm_bf16_kernel(
    const __nv_bfloat16* __restrict__ Ahg, const __nv_bfloat16* __restrict__ Alg,
    const __nv_bfloat16* __restrict__ Whg, const __nv_bfloat16* __restrict__ Wlg,
    const float* __restrict__ b1, const float* __restrict__ b2,
    float* __restrict__ C, int N)
{
    extern __shared__ char dynsmem[];
    __nv_bfloat16* sAh = (__nv_bfloat16*)dynsmem;
    __nv_bfloat16* sAl = sAh + 128 * SROW;
    __nv_bfloat16* sWh = sAl + 128 * SROW;
    __nv_bfloat16* sWl = sWh + 128 * SROW;

    const int m0 = blockIdx.y << 7;
    const int n0 = blockIdx.x << 7;
    const int tid = (int)threadIdx.x;
    const int wid = tid >> 5;
    const int lane = tid & 31;
    const int wm0 = (wid >> 2) << 6;
    const int wn0 = (wid & 3) << 5;

    const int arow = (lane & 7) + (((lane >> 3) & 1) << 3);
    const int acol = (lane >> 4) << 3;
    const int brow = (lane & 7) + ((lane >> 4) << 3);
    const int bcol = ((lane >> 3) & 1) << 3;

    const uint32_t sAh0 = (uint32_t)__cvta_generic_to_shared(sAh) + (uint32_t)(((wm0 + arow) * SROW + acol) * 2);
    const uint32_t sAl0 = (uint32_t)__cvta_generic_to_shared(sAl) + (uint32_t)(((wm0 + arow) * SROW + acol) * 2);
    const uint32_t sWh0 = (uint32_t)__cvta_generic_to_shared(sWh) + (uint32_t)(((wn0 + brow) * SROW + bcol) * 2);
    const uint32_t sWl0 = (uint32_t)__cvta_generic_to_shared(sWl) + (uint32_t)(((wn0 + brow) * SROW + bcol) * 2);

    float acc[16][4];
#pragma unroll
    for (int i = 0; i < 16; i++) {
#pragma unroll
        for (int j = 0; j < 4; j++) { acc[i][j] = 0.f; }
    }

    const int lr = tid >> 1;
    const int lc = (tid & 1) << 5;

    for (int kc = 0; kc < 4; kc++) {
        const __nv_bfloat16* ag = Ahg + (size_t)(m0 + lr) * 256 + kc * 64 + lc;
        const __nv_bfloat16* al = Alg + (size_t)(m0 + lr) * 256 + kc * 64 + lc;
        const __nv_bfloat16* wg = Whg + (size_t)(n0 + lr) * 256 + kc * 64 + lc;
        const __nv_bfloat16* wl = Wlg + (size_t)(n0 + lr) * 256 + kc * 64 + lc;
        __nv_bfloat16* dA_h = sAh + lr * SROW + lc;
        __nv_bfloat16* dA_l = sAl + lr * SROW + lc;
        __nv_bfloat16* dW_h = sWh + lr * SROW + lc;
        __nv_bfloat16* dW_l = sWl + lr * SROW + lc;
#pragma unroll
        for (int q = 0; q < 4; q++) {
            ((uint4*)(dA_h + q * 8))[0] = ((const uint4*)(ag + q * 8))[0];
            ((uint4*)(dA_l + q * 8))[0] = ((const uint4*)(al + q * 8))[0];
            ((uint4*)(dW_h + q * 8))[0] = ((const uint4*)(wg + q * 8))[0];
            ((uint4*)(dW_l + q * 8))[0] = ((const uint4*)(wl + q * 8))[0];
        }
        __syncthreads();

#pragma unroll
        for (int ks = 0; ks < 4; ks++) {
            const uint32_t koff = (uint32_t)(ks * 32);
            uint32_t afr[4][4];
            uint32_t bh[4][2];
            uint32_t bl[4][2];
#pragma unroll
            for (int fp = 0; fp < 2; fp++) {
                uint32_t tmp[4];
                ldsm_x4(tmp, sWh0 + (uint32_t)(fp * 16 * SROW * 2) + koff);
                bh[2 * fp][0] = tmp[0];
                bh[2 * fp][1] = tmp[1];
                bh[2 * fp + 1][0] = tmp[2];
                bh[2 * fp + 1][1] = tmp[3];
                ldsm_x4(tmp, sWl0 + (uint32_t)(fp * 16 * SROW * 2) + koff);
                bl[2 * fp][0] = tmp[0];
                bl[2 * fp][1] = tmp[1];
                bl[2 * fp + 1][0] = tmp[2];
                bl[2 * fp + 1][1] = tmp[3];
            }
#pragma unroll
            for (int fm = 0; fm < 4; fm++) {
                ldsm_x4(afr[fm], sAh0 + (uint32_t)(fm * 16 * SROW * 2) + koff);
            }
#pragma unroll
            for (int fm = 0; fm < 4; fm++) {
#pragma unroll
                for (int fn = 0; fn < 4; fn++) {
                    mma_bf16(acc[fm * 4 + fn], afr[fm], bh[fn]);
                    mma_bf16(acc[fm * 4 + fn], afr[fm], bl[fn]);
                }
            }
#pragma unroll
            for (int fm = 0; fm < 4; fm++) {
                ldsm_x4(afr[fm], sAl0 + (uint32_t)(fm * 16 * SROW * 2) + koff);
            }
#pragma unroll
            for (int fm = 0; fm < 4; fm++) {
#pragma unroll
                for (int fn = 0; fn < 4; fn++) {
                    mma_bf16(acc[fm * 4 + fn], afr[fm], bh[fn]);
                }
            }
        }
        __syncthreads();
    }

#pragma unroll
    for (int fm = 0; fm < 4; fm++) {
#pragma unroll
        for (int fn = 0; fn < 4; fn++) {
            float* d = acc[fm * 4 + fn];
            int row = m0 + wm0 + fm * 16 + (lane >> 2);
            int col = n0 + wn0 + fn * 8 + ((lane & 3) << 1);
            float bv0 = b1[col];
            float bv1 = b1[col + 1];
            if (b2 != nullptr) {
                bv0 += b2[col];
                bv1 += b2[col + 1];
            }
            float2 v0 = make_float2(d[0] + bv0, d[1] + bv1);
            float2 v1 = make_float2(d[2] + bv0, d[3] + bv1);
            ((float2*)(C + (size_t)row * N + col))[0] = v0;
            ((float2*)(C + (size_t)(row + 8) * N + col))[0] = v1;
        }
    }
}

// ---------------- generic fp32 GEMM (K=128 layers) ----------------
__global__ __launch_bounds__(256, 2) void gemm_kernel(
    const float* __restrict__ A, const float* __restrict__ W,
    const float* __restrict__ b1, const float* __restrict__ b2,
    float* __restrict__ C, int N, int K, int epi)
{
    __shared__ float As[16][132];
    __shared__ float Ws[16][132];
    const int m0 = blockIdx.y << 7;
    const int n0 = blockIdx.x << 7;
    const int tid = (int)threadIdx.x;
    const int tx = tid & 15;
    const int ty = tid >> 4;
    const int lr = tid >> 2;
    const int lk = (tid & 3) << 2;

    const float* Ap0 = A + (size_t)(m0 + lr) * K + lk;
    const float* Ap1 = A + (size_t)(m0 + lr + 64) * K + lk;
    const float* Wp0 = W + (size_t)(n0 + lr) * K + lk;
    const float* Wp1 = W + (size_t)(n0 + lr + 64) * K + lk;

    float acc[8][8];
#pragma unroll
    for (int i = 0; i < 8; i++) {
#pragma unroll
        for (int j = 0; j < 8; j++) { acc[i][j] = 0.f; }
    }

    for (int k0 = 0; k0 < K; k0 += 16) {
        float4 a0 = ((const float4*)(Ap0 + k0))[0];
        float4 a1 = ((const float4*)(Ap1 + k0))[0];
        float4 w0 = ((const float4*)(Wp0 + k0))[0];
        float4 w1 = ((const float4*)(Wp1 + k0))[0];
        As[lk+0][lr] = a0.x; As[lk+1][lr] = a0.y; As[lk+2][lr] = a0.z; As[lk+3][lr] = a0.w;
        As[lk+0][lr+64] = a1.x; As[lk+1][lr+64] = a1.y; As[lk+2][lr+64] = a1.z; As[lk+3][lr+64] = a1.w;
        Ws[lk+0][lr] = w0.x; Ws[lk+1][lr] = w0.y; Ws[lk+2][lr] = w0.z; Ws[lk+3][lr] = w0.w;
        Ws[lk+0][lr+64] = w1.x; Ws[lk+1][lr+64] = w1.y; Ws[lk+2][lr+64] = w1.z; Ws[lk+3][lr+64] = w1.w;
        __syncthreads();
#pragma unroll
        for (int kk = 0; kk < 16; kk++) {
            float a[8];
            float w[8];
            ((float4*)&a[0])[0] = ((const float4*)&As[kk][ty << 3])[0];
            ((float4*)&a[4])[0] = ((const float4*)&As[kk][(ty << 3) + 4])[0];
            ((float4*)&w[0])[0] = ((const float4*)&Ws[kk][tx << 3])[0];
            ((float4*)&w[4])[0] = ((const float4*)&Ws[kk][(tx << 3) + 4])[0];
#pragma unroll
            for (int i = 0; i < 8; i++) {
#pragma unroll
                for (int j = 0; j < 8; j++) {
                    acc[i][j] = fmaf(a[i], w[j], acc[i][j]);
                }
            }
        }
        __syncthreads();
    }

    float bias[8];
#pragma unroll
    for (int j = 0; j < 8; j++) {
        int n = n0 + (tx << 3) + j;
        float bv = (b1 != nullptr) ? b1[n] : 0.f;
        if (b2 != nullptr) { bv += b2[n]; }
        bias[j] = bv;
    }
#pragma unroll
    for (int i = 0; i < 8; i++) {
        int m = m0 + (ty << 3) + i;
        float v[8];
#pragma unroll
        for (int j = 0; j < 8; j++) {
            float t = acc[i][j] + bias[j];
            if (epi == 1) { t = 1.f / (1.f + expf(-t)); }
            else if (epi == 2) { t = fmaxf(t, 0.f); }
            v[j] = t;
        }
        float* cp = C + (size_t)m * N + n0 + (tx << 3);
        ((float4*)cp)[0]       = make_float4(v[0], v[1], v[2], v[3]);
        ((float4*)(cp + 4))[0] = make_float4(v[4], v[5], v[6], v[7]);
    }
}

// ---------------- spatial-attention softmax + scale ----------------
__global__ void sa_softmax_kernel(const float* __restrict__ xb, float* __restrict__ sx)
{
    int row = blockIdx.x;
    int f = threadIdx.x;
    size_t idx = ((size_t)row << 7) + f;
    float e = expf(sx[idx]);
    float sum = e;
#pragma unroll
    for (int o = 16; o > 0; o >>= 1) { sum += __shfl_xor_sync(0xffffffffu, sum, o); }
    __shared__ float red[4];
    if ((f & 31) == 0) { red[f >> 5] = sum; }
    __syncthreads();
    float tot = red[0] + red[1] + red[2] + red[3];
    sx[idx] = xb[idx] * e / tot;
}

// ---------------- persistent LSTM layer (tensor-core recurrent GEMM) ----------------
// 128 blocks (16 u-tiles x 8 b-tiles), 256 threads. Whh tile converted to bf16 hi/lo in
// smem once. Each step: S[32b x 64g] = h*Whh^T via m16n8k16 bf16 3-product split
// (Sh*Wh + Sh*Wl + Sl*Wh, fp32 accum). h circulates as bf16 hi/lo in ping-pong globals;
// hall (fp32) written each step. c-state in smem. Grid barrier between steps.
__global__ __launch_bounds__(256) void lstm_persist_kernel(
    const float* __restrict__ G, const float* __restrict__ Whh,
    __nv_bfloat16* __restrict__ h16h, __nv_bfloat16* __restrict__ h16l,
    float* __restrict__ hall, unsigned nb)
{
    extern __shared__ char dynsmem[];
    __nv_bfloat16* wsh = (__nv_bfloat16*)dynsmem;    // [64][SROWK] Whh hi (row c=gate*16+uu)
    __nv_bfloat16* wsl = wsh + 64 * SROWK;           // [64][SROWK] Whh lo
    __nv_bfloat16* hsh = wsl + 64 * SROWK;           // [32][SROWK] h hi (row bb)
    __nv_bfloat16* hsl = hsh + 32 * SROWK;           // [32][SROWK] h lo
    float* Ssm = (float*)(hsl + 32 * SROWK);         // [32][68] preactivations
    float* csm = Ssm + 32 * 68;                      // [32][18] c state

    const int u0 = blockIdx.x << 4;
    const int b0 = blockIdx.y << 5;
    const int tid = (int)threadIdx.x;
    const int wid = tid >> 5;
    const int lane = tid & 31;

    // one-time: convert Whh tile fp32 -> bf16 hi/lo in smem; zero c
#pragma unroll 4
    for (int i = 0; i < 16; i++) {
        int f4 = tid + (i << 8);                 // 0..4095
        int c  = f4 >> 6;                        // 0..63
        int kq = (f4 & 63) << 2;                 // 0..252
        int wrow = ((c >> 4) << 8) + u0 + (c & 15);
        float4 v = ((const float4*)(Whh + (size_t)wrow * Hn + kq))[0];
        __nv_bfloat162 h0 = __floats2bfloat162_rn(v.x, v.y);
        __nv_bfloat162 h1 = __floats2bfloat162_rn(v.z, v.w);
        float lx = v.x - __bfloat162float(__low2bfloat16(h0));
        float ly = v.y - __bfloat162float(__high2bfloat16(h0));
        float lz = v.z - __bfloat162float(__low2bfloat16(h1));
        float lw = v.w - __bfloat162float(__high2bfloat16(h1));
        ((__nv_bfloat162*)(wsh + c * SROWK + kq))[0] = h0;
        ((__nv_bfloat162*)(wsh + c * SROWK + kq))[1] = h1;
        ((__nv_bfloat162*)(wsl + c * SROWK + kq))[0] = __floats2bfloat162_rn(lx, ly);
        ((__nv_bfloat162*)(wsl + c * SROWK + kq))[1] = __floats2bfloat162_rn(lz, lw);
    }
    for (int i = tid; i < 32 * 18; i += 256) { csm[i] = 0.f; }
    __syncthreads();

    // ldmatrix base addresses
    const int lane15 = lane & 15;
    const uint32_t aBaseH = (uint32_t)__cvta_generic_to_shared(hsh)
                          + (uint32_t)((lane15 * SROWK + ((lane >> 4) << 3)) * 2);
    const uint32_t aBaseL = (uint32_t)__cvta_generic_to_shared(hsl)
                          + (uint32_t)((lane15 * SROWK + ((lane >> 4) << 3)) * 2);
    const uint32_t bBaseH = (uint32_t)__cvta_generic_to_shared(wsh)
                          + (uint32_t)((((wid << 3) + (lane15 & 7)) * SROWK + (((lane15 >> 3) & 1) << 3)) * 2);
    const uint32_t bBaseL = (uint32_t)__cvta_generic_to_shared(wsl)
                          + (uint32_t)((((wid << 3) + (lane15 & 7)) * SROWK + (((lane15 >> 3) & 1) << 3)) * 2);

    // gate-phase cell mapping: 2 consecutive cells per thread
    const int uu = (tid << 1) & 15;
    const int bb = tid >> 3;
    const int gb = b0 + bb;
    const int gu = u0 + uu;

    unsigned target = 0;
    for (int t = 0; t < Tn; t++) {
        // prefetch gate preactivations
        float2 gqi, gqf, gqg, gqo;
        {
            const float* gp = G + (((size_t)gb * Tn + t) << 10) + gu;
            gqi = ((const float2*)(gp +   0))[0];
            gqf = ((const float2*)(gp + 256))[0];
            gqg = ((const float2*)(gp + 512))[0];
            gqo = ((const float2*)(gp + 768))[0];
        }

        float acc0[4];
        float acc1[4];
#pragma unroll
        for (int j = 0; j < 4; j++) { acc0[j] = 0.f; acc1[j] = 0.f; }

        if (t > 0) {
            // stage h bf16 hi/lo tiles [32 x 256] (L2-coherent loads)
            const __nv_bfloat16* hph = h16h + (size_t)(t & 1) * BH;
            const __nv_bfloat16* hpl = h16l + (size_t)(t & 1) * BH;
#pragma unroll 4
            for (int i = 0; i < 4; i++) {
                int f4 = tid + (i << 8);          // 0..1023
                int hbb = f4 >> 5;                // 0..31
                int k8 = (f4 & 31) << 3;          // 0..248
                uint4 vh = __ldcg((const uint4*)(hph + (size_t)(b0 + hbb) * Hn + k8));
                uint4 vl = __ldcg((const uint4*)(hpl + (size_t)(b0 + hbb) * Hn + k8));
                ((uint4*)(hsh + hbb * SROWK + k8))[0] = vh;
                ((uint4*)(hsl + hbb * SROWK + k8))[0] = vl;
            }
            __syncthreads();

            // MMA: warp wid computes n-strip [wid*8, wid*8+8), M=32, K=256
#pragma unroll
            for (int ks = 0; ks < 16; ks++) {
                const uint32_t koff = (uint32_t)(ks * 32);
                uint32_t bh[2];
                uint32_t bl[2];
                uint32_t a0[4];
                uint32_t a1[4];
                ldsm_x2(bh, bBaseH + koff);
                ldsm_x2(bl, bBaseL + koff);
                ldsm_x4(a0, aBaseH + koff);
                ldsm_x4(a1, aBaseH + (uint32_t)(16 * SROWK * 2) + koff);
                mma_bf16(acc0, a0, bh);
                mma_bf16(acc1, a1, bh);
                mma_bf16(acc0, a0, bl);
                mma_bf16(acc1, a1, bl);
                ldsm_x4(a0, aBaseL + koff);
                ldsm_x4(a1, aBaseL + (uint32_t)(16 * SROWK * 2) + koff);
                mma_bf16(acc0, a0, bh);
                mma_bf16(acc1, a1, bh);
            }
            __syncthreads();   // hsh/hsl reads complete before next step's staging (also orders Ssm)
        }

        // deposit S: acc frag rows m = fm*16 + lane/4 (+8), cols n = wid*8 + (lane%4)*2
        {
            int r0 = lane >> 2;
            int cb = (wid << 3) + ((lane & 3) << 1);
            Ssm[(r0 +  0) * 68 + cb]     = acc0[0];
            Ssm[(r0 +  0) * 68 + cb + 1] = acc0[1];
            Ssm[(r0 +  8) * 68 + cb]     = acc0[2];
            Ssm[(r0 +  8) * 68 + cb + 1] = acc0[3];
            Ssm[(r0 + 16) * 68 + cb]     = acc1[0];
            Ssm[(r0 + 16) * 68 + cb + 1] = acc1[1];
            Ssm[(r0 + 24) * 68 + cb]     = acc1[2];
            Ssm[(r0 + 24) * 68 + cb + 1] = acc1[3];
        }
        __syncthreads();

        // gate math: 512 cells, 2 per thread
        {
            const float* S0 = Ssm + bb * 68;
            float hv[2];
            float cn[2];
            float2 cpv = ((const float2*)&csm[bb * 18 + uu])[0];
            float cprev[2] = {cpv.x, cpv.y};
            float gi2[2] = {gqi.x, gqi.y};
            float gf2[2] = {gqf.x, gqf.y};
            float gg2[2] = {gqg.x, gqg.y};
            float go2[2] = {gqo.x, gqo.y};
#pragma unroll
            for (int e = 0; e < 2; e++) {
                int ue = uu + e;
                float gi = gi2[e] + S0[ 0 + ue];
                float gf = gf2[e] + S0[16 + ue];
                float gg = gg2[e] + S0[32 + ue];
                float go = go2[e] + S0[48 + ue];
                float si = 1.f / (1.f + expf(-gi));
                float sf = 1.f / (1.f + expf(-gf));
                float so = 1.f / (1.f + expf(-go));
                float tg = tanhf(gg);
                cn[e] = sf * cprev[e] + si * tg;
                hv[e] = so * tanhf(cn[e]);
            }
            ((float2*)&csm[bb * 18 + uu])[0] = make_float2(cn[0], cn[1]);
            // h as bf16 hi/lo to ping-pong globals, fp32 to hall
            __nv_bfloat162 hh = __floats2bfloat162_rn(hv[0], hv[1]);
            float l0 = hv[0] - __bfloat162float(__low2bfloat16(hh));
            float l1 = hv[1] - __bfloat162float(__high2bfloat16(hh));
            __nv_bfloat162 hl = __floats2bfloat162_rn(l0, l1);
            size_t hoff = (size_t)((t + 1) & 1) * BH + (size_t)gb * Hn + gu;
            ((__nv_bfloat162*)(h16h + hoff))[0] = hh;
            ((__nv_bfloat162*)(h16l + hoff))[0] = hl;
            ((float2*)(hall + ((size_t)gb * Tn + t) * Hn + gu))[0] = make_float2(hv[0], hv[1]);
        }

        // grid barrier
        __syncthreads();
        __threadfence();
        target += nb;
        if (tid == 0) {
            atomicAdd(&g_bar, 1u);
            while (*((volatile unsigned*)&g_bar) < target) { }
        }
        __syncthreads();
    }
}

// ---------------- temporal attention ----------------
__global__ void ctx_kernel(const float* __restrict__ blg, const float* __restrict__ tot,
                           float* __restrict__ ctx)
{
    int gid = blockIdx.x * 256 + threadIdx.x;
    int b = gid >> 7;
    int f = gid & 127;
    const float* lp = blg + (((size_t)b * Tn) << 7) + f;
    const float* tp = tot + (((size_t)b * Tn) << 7) + f;
    float m = -1e30f;
    for (int t = 0; t < Tn; t++) { m = fmaxf(m, lp[(size_t)t << 7]); }
    float s = 0.f;
    float w = 0.f;
    for (int t = 0; t < Tn; t++) {
        float e = expf(lp[(size_t)t << 7] - m);
        s += e;
        w = fmaf(e, tp[(size_t)t << 7], w);
    }
    ctx[gid] = w / s;
}

// ---------------- final projection ----------------
__global__ void out_kernel(const float* __restrict__ ctx, const float* __restrict__ ow,
                           float* __restrict__ out)
{
    int b = blockIdx.x;
    int f = threadIdx.x;
    float v = ctx[(b << 7) + f] * ow[f];
#pragma unroll
    for (int o = 16; o > 0; o >>= 1) { v += __shfl_xor_sync(0xffffffffu, v, o); }
    __shared__ float red[4];
    if ((f & 31) == 0) { red[f >> 5] = v; }
    __syncthreads();
    if (f == 0) { out[b] = red[0] + red[1] + red[2] + red[3]; }
}

// ---------------- host ----------------
extern "C" void kernel_launch(void* const* d_in, const int* in_sizes, int n_in,
                              void* d_out, int out_size)
{
    (void)in_sizes; (void)n_in; (void)out_size;
    const float* x    = (const float*)d_in[0];
    const float* bng  = (const float*)d_in[1];
    const float* bnb  = (const float*)d_in[2];
    const float* bnm  = (const float*)d_in[3];
    const float* bnv  = (const float*)d_in[4];
    const float* saW  = (const float*)d_in[5];
    const float* sab  = (const float*)d_in[6];
    const float* inW  = (const float*)d_in[7];
    const float* inb  = (const float*)d_in[8];
    const float* Wih0 = (const float*)d_in[9];
    const float* Whh0 = (const float*)d_in[10];
    const float* bih0 = (const float*)d_in[11];
    const float* bhh0 = (const float*)d_in[12];
    const float* Wih1 = (const float*)d_in[13];
    const float* Whh1 = (const float*)d_in[14];
    const float* bih1 = (const float*)d_in[15];
    const float* bhh1 = (const float*)d_in[16];
    const float* tahW = (const float*)d_in[17];
    const float* tahb = (const float*)d_in[18];
    const float* taW  = (const float*)d_in[19];
    const float* tab  = (const float*)d_in[20];
    const float* outW = (const float*)d_in[21];

    float *pF1, *pF2, *pH1, *pH2, *pG, *pCtx;
    unsigned* pBar;
    __nv_bfloat16 *pAh, *pAl, *pWh, *pWl, *pHh, *pHl;
    cudaGetSymbolAddress((void**)&pF1, g_bufF1);
    cudaGetSymbolAddress((void**)&pF2, g_bufF2);
    cudaGetSymbolAddress((void**)&pH1, g_bufH1);
    cudaGetSymbolAddress((void**)&pH2, g_bufH2);
    cudaGetSymbolAddress((void**)&pG,  g_bufG);
    cudaGetSymbolAddress((void**)&pCtx, g_ctxbuf);
    cudaGetSymbolAddress((void**)&pBar, g_bar);
    cudaGetSymbolAddress((void**)&pAh, g_a16h);
    cudaGetSymbolAddress((void**)&pAl, g_a16l);
    cudaGetSymbolAddress((void**)&pWh, g_w16h);
    cudaGetSymbolAddress((void**)&pWl, g_w16l);
    cudaGetSymbolAddress((void**)&pHh, g_h16h);
    cudaGetSymbolAddress((void**)&pHl, g_h16l);

    const int lstm_smem = (64 * SROWK + 64 * SROWK + 32 * SROWK + 32 * SROWK) * 2
                        + (32 * 68 + 32 * 18) * 4;   // ~112 KB
    cudaFuncSetAttribute(lstm_persist_kernel,
                         cudaFuncAttributeMaxDynamicSharedMemorySize, lstm_smem);
    const int bf16_smem = 4 * 128 * SROW * 2;
    cudaFuncSetAttribute(gemm_bf16_kernel,
                         cudaFuncAttributeMaxDynamicSharedMemorySize, bf16_smem);

    const int SPLIT_A_BLKS = (BT * Hn / 4) / 256;
    const int SPLIT_W_BLKS = (4 * Hn * Hn / 4) / 256;
    const int SPLIT_T_BLKS = (Fn * Hn / 4) / 256;

    // 1) BN
    bn_kernel<<<(BT * Fn / 4) / 256, 256>>>((const float4*)x, (const float4*)bng,
        (const float4*)bnb, (const float4*)bnm, (const float4*)bnv, (float4*)pF1);

    // 2) SA logits
    gemm_kernel<<<dim3(1, BT / 128), 256>>>(pF1, saW, sab, nullptr, pF2, Fn, Fn, 1);

    // 3) softmax + scale
    sa_softmax_kernel<<<BT, 128>>>(pF1, pF2);

    // 4) layer_in
    gemm_kernel<<<dim3(2, BT / 128), 256>>>(pF2, inW, inb, nullptr, pH1, Hn, Fn, 0);

    // 5) LSTM layer 0
    split_kernel<<<SPLIT_A_BLKS, 256>>>((const float4*)pH1, (__nv_bfloat162*)pAh, (__nv_bfloat162*)pAl);
    split_kernel<<<SPLIT_W_BLKS, 256>>>((const float4*)Wih0, (__nv_bfloat162*)pWh, (__nv_bfloat162*)pWl);
    gemm_bf16_kernel<<<dim3(8, BT / 128), 256, bf16_smem>>>(pAh, pAl, pWh, pWl, bih0, bhh0, pG, 4 * Hn);
    cudaMemsetAsync(pBar, 0, sizeof(unsigned));
    lstm_persist_kernel<<<dim3(16, 8), 256, lstm_smem>>>(pG, Whh0, pHh, pHl, pH2, 128u);

    // 6) LSTM layer 1
    split_kernel<<<SPLIT_A_BLKS, 256>>>((const float4*)pH2, (__nv_bfloat162*)pAh, (__nv_bfloat162*)pAl);
    split_kernel<<<SPLIT_W_BLKS, 256>>>((const float4*)Wih1, (__nv_bfloat162*)pWh, (__nv_bfloat162*)pWl);
    gemm_bf16_kernel<<<dim3(8, BT / 128), 256, bf16_smem>>>(pAh, pAl, pWh, pWl, bih1, bhh1, pG, 4 * Hn);
    cudaMemsetAsync(pBar, 0, sizeof(unsigned));
    lstm_persist_kernel<<<dim3(16, 8), 256, lstm_smem>>>(pG, Whh1, pHh, pHl, pH1, 128u);

    // 7) temporal attention
    split_kernel<<<SPLIT_A_BLKS, 256>>>((const float4*)pH1, (__nv_bfloat162*)pAh, (__nv_bfloat162*)pAl);
    split_kernel<<<SPLIT_T_BLKS, 256>>>((const float4*)tahW, (__nv_bfloat162*)pWh, (__nv_bfloat162*)pWl);
    gemm_bf16_kernel<<<dim3(1, BT / 128), 256, bf16_smem>>>(pAh, pAl, pWh, pWl, tahb, nullptr, pF1, Fn);
    gemm_kernel<<<dim3(1, BT / 128), 256>>>(pF1, taW, tab, nullptr, pF2, Fn, Fn, 2);
    ctx_kernel<<<(Bn * Fn) / 256, 256>>>(pF2, pF1, pCtx);

    // 8) output
    out_kernel<<<Bn, 128>>>(pCtx, outW, (float*)d_out);
}

// round 9
// speedup vs baseline: 2.4867x; 1.0559x over previous
#include <cuda_runtime.h>
#include <cuda_bf16.h>
#include <cstdint>

#define Bn 256
#define Tn 512
#define Fn 128
#define Hn 256
#define BT (Bn*Tn)
#define BH (Bn*Hn)
#define SROW 72
#define SROWK 264   // LSTM smem row stride (256 k + 8 pad)

// weight split buffer offsets (elements)
#define W_SA   0
#define W_IN   16384
#define W_IH0  49152
#define W_IH1  311296
#define W_TAH  573440
#define W_TA   606208
#define W_TOT  622592

// ---------------- scratch (device globals) ----------------
__device__ float g_bufF1[(size_t)BT * Fn];
__device__ float g_bufF2[(size_t)BT * Fn];
__device__ float g_bufG [(size_t)BT * 4 * Hn];
__device__ float g_ctxbuf[Bn * Fn];
__device__ unsigned g_bar;
__device__ __nv_bfloat16 g_a16h[(size_t)BT * Hn];   // activation pair buffer A1
__device__ __nv_bfloat16 g_a16l[(size_t)BT * Hn];
__device__ __nv_bfloat16 g_b16h[(size_t)BT * Hn];   // activation pair buffer A2
__device__ __nv_bfloat16 g_b16l[(size_t)BT * Hn];
__device__ __nv_bfloat16 g_w16h[W_TOT];             // all weights hi
__device__ __nv_bfloat16 g_w16l[W_TOT];             // all weights lo
__device__ __nv_bfloat16 g_h16h[2 * BH];            // ping-pong h (bf16 hi)
__device__ __nv_bfloat16 g_h16l[2 * BH];            // ping-pong h (bf16 lo)

// ---------------- BatchNorm (eval) + bf16 pair emit ----------------
__global__ void bn_kernel(const float4* __restrict__ x, const float4* __restrict__ g,
                          const float4* __restrict__ bt, const float4* __restrict__ mn,
                          const float4* __restrict__ vr, float4* __restrict__ out,
                          __nv_bfloat162* __restrict__ oh, __nv_bfloat162* __restrict__ ol)
{
    int i = blockIdx.x * 256 + threadIdx.x;
    int fi = i & 31;
    float4 xv = x[i];
    float4 gv = g[fi];
    float4 bv = bt[fi];
    float4 mv = mn[fi];
    float4 vv = vr[fi];
    float4 r;
    r.x = (xv.x - mv.x) * rsqrtf(vv.x + 1e-5f) * gv.x + bv.x;
    r.y = (xv.y - mv.y) * rsqrtf(vv.y + 1e-5f) * gv.y + bv.y;
    r.z = (xv.z - mv.z) * rsqrtf(vv.z + 1e-5f) * gv.z + bv.z;
    r.w = (xv.w - mv.w) * rsqrtf(vv.w + 1e-5f) * gv.w + bv.w;
    out[i] = r;
    __nv_bfloat162 h0 = __floats2bfloat162_rn(r.x, r.y);
    __nv_bfloat162 h1 = __floats2bfloat162_rn(r.z, r.w);
    float lx = r.x - __bfloat162float(__low2bfloat16(h0));
    float ly = r.y - __bfloat162float(__high2bfloat16(h0));
    float lz = r.z - __bfloat162float(__low2bfloat16(h1));
    float lw = r.w - __bfloat162float(__high2bfloat16(h1));
    oh[2 * i]     = h0;
    oh[2 * i + 1] = h1;
    ol[2 * i]     = __floats2bfloat162_rn(lx, ly);
    ol[2 * i + 1] = __floats2bfloat162_rn(lz, lw);
}

// ---------------- fp32 -> bf16 hi/lo split (weights) ----------------
__global__ void split_kernel(const float4* __restrict__ x,
                             __nv_bfloat162* __restrict__ hh,
                             __nv_bfloat162* __restrict__ ll)
{
    int i = blockIdx.x * 256 + threadIdx.x;
    float4 v = x[i];
    __nv_bfloat162 h0 = __floats2bfloat162_rn(v.x, v.y);
    __nv_bfloat162 h1 = __floats2bfloat162_rn(v.z, v.w);
    float lx = v.x - __bfloat162float(__low2bfloat16(h0));
    float ly = v.y - __bfloat162float(__high2bfloat16(h0));
    float lz = v.z - __bfloat162float(__low2bfloat16(h1));
    float lw = v.w - __bfloat162float(__high2bfloat16(h1));
    hh[2 * i]     = h0;
    hh[2 * i + 1] = h1;
    ll[2 * i]     = __floats2bfloat162_rn(lx, ly);
    ll[2 * i + 1] = __floats2bfloat162_rn(lz, lw);
}

// ---------------- tensor-core helpers ----------------
__device__ __forceinline__ void ldsm_x4(uint32_t* r, uint32_t saddr)
{
    asm volatile("ldmatrix.sync.aligned.m8n8.x4.shared.b16 {%0,%1,%2,%3}, [%4];"
                 : "=r"(r[0]), "=r"(r[1]), "=r"(r[2]), "=r"(r[3]) : "r"(saddr));
}

__device__ __forceinline__ void ldsm_x2(uint32_t* r, uint32_t saddr)
{
    asm volatile("ldmatrix.sync.aligned.m8n8.x2.shared.b16 {%0,%1}, [%2];"
                 : "=r"(r[0]), "=r"(r[1]) : "r"(saddr));
}

__device__ __forceinline__ void mma_bf16(float* d, const uint32_t* a, const uint32_t* b)
{
    asm volatile("mma.sync.aligned.m16n8k16.row.col.f32.bf16.bf16.f32 "
                 "{%0,%1,%2,%3}, {%4,%5,%6,%7}, {%8,%9}, {%0,%1,%2,%3};"
                 : "+f"(d[0]), "+f"(d[1]), "+f"(d[2]), "+f"(d[3])
                 : "r"(a[0]), "r"(a[1]), "r"(a[2]), "r"(a[3]), "r"(b[0]), "r"(b[1]));
}

// ---------------- unified bf16-split tensor GEMM ----------------
// C[M,N] = A[M,K]@W[N,K]^T + b1 (+b2); 3-product split; K in {128,256};
// epi: 0 none, 1 sigmoid, 2 relu; outputs: Cf (fp32, may be null) and/or Chi/Clo (bf16 pair).
__global__ __launch_bounds__(256) void gemm_bf16_kernel(
    const __nv_bfloat16* __restrict__ Ahg, const __nv_bfloat16* __restrict__ Alg,
    const __nv_bfloat16* __restrict__ Whg, const __nv_bfloat16* __restrict__ Wlg,
    const float* __restrict__ b1, const float* __restrict__ b2,
    float* __restrict__ Cf, __nv_bfloat16* __restrict__ Chi, __nv_bfloat16* __restrict__ Clo,
    int N, int K, int epi)
{
    extern __shared__ char dynsmem[];
    __nv_bfloat16* sAh = (__nv_bfloat16*)dynsmem;
    __nv_bfloat16* sAl = sAh + 128 * SROW;
    __nv_bfloat16* sWh = sAl + 128 * SROW;
    __nv_bfloat16* sWl = sWh + 128 * SROW;

    const int m0 = blockIdx.y << 7;
    const int n0 = blockIdx.x << 7;
    const int tid = (int)threadIdx.x;
    const int wid = tid >> 5;
    const int lane = tid & 31;
    const int wm0 = (wid >> 2) << 6;
    const int wn0 = (wid & 3) << 5;

    const int arow = (lane & 7) + (((lane >> 3) & 1) << 3);
    const int acol = (lane >> 4) << 3;
    const int brow = (lane & 7) + ((lane >> 4) << 3);
    const int bcol = ((lane >> 3) & 1) << 3;

    const uint32_t sAh0 = (uint32_t)__cvta_generic_to_shared(sAh) + (uint32_t)(((wm0 + arow) * SROW + acol) * 2);
    const uint32_t sAl0 = (uint32_t)__cvta_generic_to_shared(sAl) + (uint32_t)(((wm0 + arow) * SROW + acol) * 2);
    const uint32_t sWh0 = (uint32_t)__cvta_generic_to_shared(sWh) + (uint32_t)(((wn0 + brow) * SROW + bcol) * 2);
    const uint32_t sWl0 = (uint32_t)__cvta_generic_to_shared(sWl) + (uint32_t)(((wn0 + brow) * SROW + bcol) * 2);

    float acc[16][4];
#pragma unroll
    for (int i = 0; i < 16; i++) {
#pragma unroll
        for (int j = 0; j < 4; j++) { acc[i][j] = 0.f; }
    }

    const int lr = tid >> 1;
    const int lc = (tid & 1) << 5;
    const int nkc = K >> 6;

    for (int kc = 0; kc < nkc; kc++) {
        const __nv_bfloat16* ag = Ahg + (size_t)(m0 + lr) * K + kc * 64 + lc;
        const __nv_bfloat16* al = Alg + (size_t)(m0 + lr) * K + kc * 64 + lc;
        const __nv_bfloat16* wg = Whg + (size_t)(n0 + lr) * K + kc * 64 + lc;
        const __nv_bfloat16* wl = Wlg + (size_t)(n0 + lr) * K + kc * 64 + lc;
        __nv_bfloat16* dA_h = sAh + lr * SROW + lc;
        __nv_bfloat16* dA_l = sAl + lr * SROW + lc;
        __nv_bfloat16* dW_h = sWh + lr * SROW + lc;
        __nv_bfloat16* dW_l = sWl + lr * SROW + lc;
#pragma unroll
        for (int q = 0; q < 4; q++) {
            ((uint4*)(dA_h + q * 8))[0] = ((const uint4*)(ag + q * 8))[0];
            ((uint4*)(dA_l + q * 8))[0] = ((const uint4*)(al + q * 8))[0];
            ((uint4*)(dW_h + q * 8))[0] = ((const uint4*)(wg + q * 8))[0];
            ((uint4*)(dW_l + q * 8))[0] = ((const uint4*)(wl + q * 8))[0];
        }
        __syncthreads();

#pragma unroll
        for (int ks = 0; ks < 4; ks++) {
            const uint32_t koff = (uint32_t)(ks * 32);
            uint32_t afr[4][4];
            uint32_t bh[4][2];
            uint32_t bl[4][2];
#pragma unroll
            for (int fp = 0; fp < 2; fp++) {
                uint32_t tmp[4];
                ldsm_x4(tmp, sWh0 + (uint32_t)(fp * 16 * SROW * 2) + koff);
                bh[2 * fp][0] = tmp[0];
                bh[2 * fp][1] = tmp[1];
                bh[2 * fp + 1][0] = tmp[2];
                bh[2 * fp + 1][1] = tmp[3];
                ldsm_x4(tmp, sWl0 + (uint32_t)(fp * 16 * SROW * 2) + koff);
                bl[2 * fp][0] = tmp[0];
                bl[2 * fp][1] = tmp[1];
                bl[2 * fp + 1][0] = tmp[2];
                bl[2 * fp + 1][1] = tmp[3];
            }
#pragma unroll
            for (int fm = 0; fm < 4; fm++) {
                ldsm_x4(afr[fm], sAh0 + (uint32_t)(fm * 16 * SROW * 2) + koff);
            }
#pragma unroll
            for (int fm = 0; fm < 4; fm++) {
#pragma unroll
                for (int fn = 0; fn < 4; fn++) {
                    mma_bf16(acc[fm * 4 + fn], afr[fm], bh[fn]);
                    mma_bf16(acc[fm * 4 + fn], afr[fm], bl[fn]);
                }
            }
#pragma unroll
            for (int fm = 0; fm < 4; fm++) {
                ldsm_x4(afr[fm], sAl0 + (uint32_t)(fm * 16 * SROW * 2) + koff);
            }
#pragma unroll
            for (int fm = 0; fm < 4; fm++) {
#pragma unroll
                for (int fn = 0; fn < 4; fn++) {
                    mma_bf16(acc[fm * 4 + fn], afr[fm], bh[fn]);
                }
            }
        }
        __syncthreads();
    }

#pragma unroll
    for (int fm = 0; fm < 4; fm++) {
#pragma unroll
        for (int fn = 0; fn < 4; fn++) {
            float* d = acc[fm * 4 + fn];
            int row = m0 + wm0 + fm * 16 + (lane >> 2);
            int col = n0 + wn0 + fn * 8 + ((lane & 3) << 1);
            float bv0 = b1[col];
            float bv1 = b1[col + 1];
            if (b2 != nullptr) {
                bv0 += b2[col];
                bv1 += b2[col + 1];
            }
            float v00 = d[0] + bv0;
            float v01 = d[1] + bv1;
            float v10 = d[2] + bv0;
            float v11 = d[3] + bv1;
            if (epi == 1) {
                v00 = 1.f / (1.f + expf(-v00));
                v01 = 1.f / (1.f + expf(-v01));
                v10 = 1.f / (1.f + expf(-v10));
                v11 = 1.f / (1.f + expf(-v11));
            } else if (epi == 2) {
                v00 = fmaxf(v00, 0.f);
                v01 = fmaxf(v01, 0.f);
                v10 = fmaxf(v10, 0.f);
                v11 = fmaxf(v11, 0.f);
            }
            if (Cf != nullptr) {
                ((float2*)(Cf + (size_t)row * N + col))[0]       = make_float2(v00, v01);
                ((float2*)(Cf + (size_t)(row + 8) * N + col))[0] = make_float2(v10, v11);
            }
            if (Chi != nullptr) {
                __nv_bfloat162 h0 = __floats2bfloat162_rn(v00, v01);
                __nv_bfloat162 h1 = __floats2bfloat162_rn(v10, v11);
                float l00 = v00 - __bfloat162float(__low2bfloat16(h0));
                float l01 = v01 - __bfloat162float(__high2bfloat16(h0));
                float l10 = v10 - __bfloat162float(__low2bfloat16(h1));
                float l11 = v11 - __bfloat162float(__high2bfloat16(h1));
                ((__nv_bfloat162*)(Chi + (size_t)row * N + col))[0]       = h0;
                ((__nv_bfloat162*)(Chi + (size_t)(row + 8) * N + col))[0] = h1;
                ((__nv_bfloat162*)(Clo + (size_t)row * N + col))[0]       = __floats2bfloat162_rn(l00, l01);
                ((__nv_bfloat162*)(Clo + (size_t)(row + 8) * N + col))[0] = __floats2bfloat162_rn(l10, l11);
            }
        }
    }
}

// ---------------- spatial-attention softmax + scale, emits xs as bf16 pair ----------------
__global__ void sa_softmax_kernel(const float* __restrict__ xb, const float* __restrict__ sx,
                                  __nv_bfloat16* __restrict__ oh, __nv_bfloat16* __restrict__ ol)
{
    int row = blockIdx.x;
    int f = threadIdx.x;
    size_t idx = ((size_t)row << 7) + f;
    float e = expf(sx[idx]);
    float sum = e;
#pragma unroll
    for (int o = 16; o > 0; o >>= 1) { sum += __shfl_xor_sync(0xffffffffu, sum, o); }
    __shared__ float red[4];
    if ((f & 31) == 0) { red[f >> 5] = sum; }
    __syncthreads();
    float tot = red[0] + red[1] + red[2] + red[3];
    float v = xb[idx] * e / tot;
    __nv_bfloat16 hi = __float2bfloat16(v);
    __nv_bfloat16 lo = __float2bfloat16(v - __bfloat162float(hi));
    oh[idx] = hi;
    ol[idx] = lo;
}

// ---------------- persistent LSTM layer (tensor-core recurrent GEMM) ----------------
__global__ __launch_bounds__(256) void lstm_persist_kernel(
    const float* __restrict__ G, const float* __restrict__ Whh,
    __nv_bfloat16* __restrict__ h16h, __nv_bfloat16* __restrict__ h16l,
    __nv_bfloat16* __restrict__ hallh, __nv_bfloat16* __restrict__ halll, unsigned nb)
{
    extern __shared__ char dynsmem[];
    __nv_bfloat16* wsh = (__nv_bfloat16*)dynsmem;
    __nv_bfloat16* wsl = wsh + 64 * SROWK;
    __nv_bfloat16* hsh = wsl + 64 * SROWK;
    __nv_bfloat16* hsl = hsh + 32 * SROWK;
    float* Ssm = (float*)(hsl + 32 * SROWK);
    float* csm = Ssm + 32 * 68;

    const int u0 = blockIdx.x << 4;
    const int b0 = blockIdx.y << 5;
    const int tid = (int)threadIdx.x;
    const int wid = tid >> 5;
    const int lane = tid & 31;

#pragma unroll 4
    for (int i = 0; i < 16; i++) {
        int f4 = tid + (i << 8);
        int c  = f4 >> 6;
        int kq = (f4 & 63) << 2;
        int wrow = ((c >> 4) << 8) + u0 + (c & 15);
        float4 v = ((const float4*)(Whh + (size_t)wrow * Hn + kq))[0];
        __nv_bfloat162 h0 = __floats2bfloat162_rn(v.x, v.y);
        __nv_bfloat162 h1 = __floats2bfloat162_rn(v.z, v.w);
        float lx = v.x - __bfloat162float(__low2bfloat16(h0));
        float ly = v.y - __bfloat162float(__high2bfloat16(h0));
        float lz = v.z - __bfloat162float(__low2bfloat16(h1));
        float lw = v.w - __bfloat162float(__high2bfloat16(h1));
        ((__nv_bfloat162*)(wsh + c * SROWK + kq))[0] = h0;
        ((__nv_bfloat162*)(wsh + c * SROWK + kq))[1] = h1;
        ((__nv_bfloat162*)(wsl + c * SROWK + kq))[0] = __floats2bfloat162_rn(lx, ly);
        ((__nv_bfloat162*)(wsl + c * SROWK + kq))[1] = __floats2bfloat162_rn(lz, lw);
    }
    for (int i = tid; i < 32 * 18; i += 256) { csm[i] = 0.f; }
    __syncthreads();

    const int lane15 = lane & 15;
    const uint32_t aBaseH = (uint32_t)__cvta_generic_to_shared(hsh)
                          + (uint32_t)((lane15 * SROWK + ((lane >> 4) << 3)) * 2);
    const uint32_t aBaseL = (uint32_t)__cvta_generic_to_shared(hsl)
                          + (uint32_t)((lane15 * SROWK + ((lane >> 4) << 3)) * 2);
    const uint32_t bBaseH = (uint32_t)__cvta_generic_to_shared(wsh)
                          + (uint32_t)((((wid << 3) + (lane15 & 7)) * SROWK + (((lane15 >> 3) & 1) << 3)) * 2);
    const uint32_t bBaseL = (uint32_t)__cvta_generic_to_shared(wsl)
                          + (uint32_t)((((wid << 3) + (lane15 & 7)) * SROWK + (((lane15 >> 3) & 1) << 3)) * 2);

    const int uu = (tid << 1) & 15;
    const int bb = tid >> 3;
    const int gb = b0 + bb;
    const int gu = u0 + uu;

    unsigned target = 0;
    for (int t = 0; t < Tn; t++) {
        float2 gqi, gqf, gqg, gqo;
        {
            const float* gp = G + (((size_t)gb * Tn + t) << 10) + gu;
            gqi = ((const float2*)(gp +   0))[0];
            gqf = ((const float2*)(gp + 256))[0];
            gqg = ((const float2*)(gp + 512))[0];
            gqo = ((const float2*)(gp + 768))[0];
        }

        float acc0[4];
        float acc1[4];
#pragma unroll
        for (int j = 0; j < 4; j++) { acc0[j] = 0.f; acc1[j] = 0.f; }

        if (t > 0) {
            const __nv_bfloat16* hph = h16h + (size_t)(t & 1) * BH;
            const __nv_bfloat16* hpl = h16l + (size_t)(t & 1) * BH;
#pragma unroll 4
            for (int i = 0; i < 4; i++) {
                int f4 = tid + (i << 8);
                int hbb = f4 >> 5;
                int k8 = (f4 & 31) << 3;
                uint4 vh = __ldcg((const uint4*)(hph + (size_t)(b0 + hbb) * Hn + k8));
                uint4 vl = __ldcg((const uint4*)(hpl + (size_t)(b0 + hbb) * Hn + k8));
                ((uint4*)(hsh + hbb * SROWK + k8))[0] = vh;
                ((uint4*)(hsl + hbb * SROWK + k8))[0] = vl;
            }
            __syncthreads();

#pragma unroll
            for (int ks = 0; ks < 16; ks++) {
                const uint32_t koff = (uint32_t)(ks * 32);
                uint32_t bh[2];
                uint32_t bl[2];
                uint32_t a0[4];
                uint32_t a1[4];
                ldsm_x2(bh, bBaseH + koff);
                ldsm_x2(bl, bBaseL + koff);
                ldsm_x4(a0, aBaseH + koff);
                ldsm_x4(a1, aBaseH + (uint32_t)(16 * SROWK * 2) + koff);
                mma_bf16(acc0, a0, bh);
                mma_bf16(acc1, a1, bh);
                mma_bf16(acc0, a0, bl);
                mma_bf16(acc1, a1, bl);
                ldsm_x4(a0, aBaseL + koff);
                ldsm_x4(a1, aBaseL + (uint32_t)(16 * SROWK * 2) + koff);
                mma_bf16(acc0, a0, bh);
                mma_bf16(acc1, a1, bh);
            }
            __syncthreads();
        }

        {
            int r0 = lane >> 2;
            int cb = (wid << 3) + ((lane & 3) << 1);
            Ssm[(r0 +  0) * 68 + cb]     = acc0[0];
            Ssm[(r0 +  0) * 68 + cb + 1] = acc0[1];
            Ssm[(r0 +  8) * 68 + cb]     = acc0[2];
            Ssm[(r0 +  8) * 68 + cb + 1] = acc0[3];
            Ssm[(r0 + 16) * 68 + cb]     = acc1[0];
            Ssm[(r0 + 16) * 68 + cb + 1] = acc1[1];
            Ssm[(r0 + 24) * 68 + cb]     = acc1[2];
            Ssm[(r0 + 24) * 68 + cb + 1] = acc1[3];
        }
        __syncthreads();

        {
            const float* S0 = Ssm + bb * 68;
            float hv[2];
            float cn[2];
            float2 cpv = ((const float2*)&csm[bb * 18 + uu])[0];
            float cprev[2] = {cpv.x, cpv.y};
            float gi2[2] = {gqi.x, gqi.y};
            float gf2[2] = {gqf.x, gqf.y};
            float gg2[2] = {gqg.x, gqg.y};
            float go2[2] = {gqo.x, gqo.y};
#pragma unroll
            for (int e = 0; e < 2; e++) {
                int ue = uu + e;
                float gi = gi2[e] + S0[ 0 + ue];
                float gf = gf2[e] + S0[16 + ue];
                float gg = gg2[e] + S0[32 + ue];
                float go = go2[e] + S0[48 + ue];
                float si = 1.f / (1.f + expf(-gi));
                float sf = 1.f / (1.f + expf(-gf));
                float so = 1.f / (1.f + expf(-go));
                float tg = tanhf(gg);
                cn[e] = sf * cprev[e] + si * tg;
                hv[e] = so * tanhf(cn[e]);
            }
            ((float2*)&csm[bb * 18 + uu])[0] = make_float2(cn[0], cn[1]);
            __nv_bfloat162 hh = __floats2bfloat162_rn(hv[0], hv[1]);
            float l0 = hv[0] - __bfloat162float(__low2bfloat16(hh));
            float l1 = hv[1] - __bfloat162float(__high2bfloat16(hh));
            __nv_bfloat162 hl = __floats2bfloat162_rn(l0, l1);
            size_t hoff = (size_t)((t + 1) & 1) * BH + (size_t)gb * Hn + gu;
            ((__nv_bfloat162*)(h16h + hoff))[0] = hh;
            ((__nv_bfloat162*)(h16l + hoff))[0] = hl;
            size_t aoff = ((size_t)gb * Tn + t) * Hn + gu;
            ((__nv_bfloat162*)(hallh + aoff))[0] = hh;
            ((__nv_bfloat162*)(halll + aoff))[0] = hl;
        }

        __syncthreads();
        __threadfence();
        target += nb;
        if (tid == 0) {
            atomicAdd(&g_bar, 1u);
            while (*((volatile unsigned*)&g_bar) < target) { }
        }
        __syncthreads();
    }
}

// ---------------- temporal attention ----------------
__global__ void ctx_kernel(const float* __restrict__ blg, const float* __restrict__ tot,
                           float* __restrict__ ctx)
{
    int gid = blockIdx.x * 256 + threadIdx.x;
    int b = gid >> 7;
    int f = gid & 127;
    const float* lp = blg + (((size_t)b * Tn) << 7) + f;
    const float* tp = tot + (((size_t)b * Tn) << 7) + f;
    float m = -1e30f;
    for (int t = 0; t < Tn; t++) { m = fmaxf(m, lp[(size_t)t << 7]); }
    float s = 0.f;
    float w = 0.f;
    for (int t = 0; t < Tn; t++) {
        float e = expf(lp[(size_t)t << 7] - m);
        s += e;
        w = fmaf(e, tp[(size_t)t << 7], w);
    }
    ctx[gid] = w / s;
}

// ---------------- final projection ----------------
__global__ void out_kernel(const float* __restrict__ ctx, const float* __restrict__ ow,
                           float* __restrict__ out)
{
    int b = blockIdx.x;
    int f = threadIdx.x;
    float v = ctx[(b << 7) + f] * ow[f];
#pragma unroll
    for (int o = 16; o > 0; o >>= 1) { v += __shfl_xor_sync(0xffffffffu, v, o); }
    __shared__ float red[4];
    if ((f & 31) == 0) { red[f >> 5] = v; }
    __syncthreads();
    if (f == 0) { out[b] = red[0] + red[1] + red[2] + red[3]; }
}

// ---------------- host ----------------
extern "C" void kernel_launch(void* const* d_in, const int* in_sizes, int n_in,
                              void* d_out, int out_size)
{
    (void)in_sizes; (void)n_in; (void)out_size;
    const float* x    = (const float*)d_in[0];
    const float* bng  = (const float*)d_in[1];
    const float* bnb  = (const float*)d_in[2];
    const float* bnm  = (const float*)d_in[3];
    const float* bnv  = (const float*)d_in[4];
    const float* saW  = (const float*)d_in[5];
    const float* sab  = (const float*)d_in[6];
    const float* inW  = (const float*)d_in[7];
    const float* inb  = (const float*)d_in[8];
    const float* Wih0 = (const float*)d_in[9];
    const float* Whh0 = (const float*)d_in[10];
    const float* bih0 = (const float*)d_in[11];
    const float* bhh0 = (const float*)d_in[12];
    const float* Wih1 = (const float*)d_in[13];
    const float* Whh1 = (const float*)d_in[14];
    const float* bih1 = (const float*)d_in[15];
    const float* bhh1 = (const float*)d_in[16];
    const float* tahW = (const float*)d_in[17];
    const float* tahb = (const float*)d_in[18];
    const float* taW  = (const float*)d_in[19];
    const float* tab  = (const float*)d_in[20];
    const float* outW = (const float*)d_in[21];

    float *pF1, *pF2, *pG, *pCtx;
    unsigned* pBar;
    __nv_bfloat16 *pAh, *pAl, *pBh, *pBl, *pWh, *pWl, *pHh, *pHl;
    cudaGetSymbolAddress((void**)&pF1, g_bufF1);
    cudaGetSymbolAddress((void**)&pF2, g_bufF2);
    cudaGetSymbolAddress((void**)&pG,  g_bufG);
    cudaGetSymbolAddress((void**)&pCtx, g_ctxbuf);
    cudaGetSymbolAddress((void**)&pBar, g_bar);
    cudaGetSymbolAddress((void**)&pAh, g_a16h);
    cudaGetSymbolAddress((void**)&pAl, g_a16l);
    cudaGetSymbolAddress((void**)&pBh, g_b16h);
    cudaGetSymbolAddress((void**)&pBl, g_b16l);
    cudaGetSymbolAddress((void**)&pWh, g_w16h);
    cudaGetSymbolAddress((void**)&pWl, g_w16l);
    cudaGetSymbolAddress((void**)&pHh, g_h16h);
    cudaGetSymbolAddress((void**)&pHl, g_h16l);

    const int lstm_smem = (64 * SROWK + 64 * SROWK + 32 * SROWK + 32 * SROWK) * 2
                        + (32 * 68 + 32 * 18) * 4;
    cudaFuncSetAttribute(lstm_persist_kernel,
                         cudaFuncAttributeMaxDynamicSharedMemorySize, lstm_smem);
    const int bf16_smem = 4 * 128 * SROW * 2;
    cudaFuncSetAttribute(gemm_bf16_kernel,
                         cudaFuncAttributeMaxDynamicSharedMemorySize, bf16_smem);

    // 1) BN: xb -> F1 fp32 + pair A1
    bn_kernel<<<(BT * Fn / 4) / 256, 256>>>((const float4*)x, (const float4*)bng,
        (const float4*)bnb, (const float4*)bnm, (const float4*)bnv, (float4*)pF1,
        (__nv_bfloat162*)pAh, (__nv_bfloat162*)pAl);

    // weight splits (once per call, sequential into carved buffer)
    split_kernel<<<(Fn * Fn / 4) / 256, 256>>>((const float4*)saW,
        (__nv_bfloat162*)(pWh + W_SA), (__nv_bfloat162*)(pWl + W_SA));
    split_kernel<<<(Hn * Fn / 4) / 256, 256>>>((const float4*)inW,
        (__nv_bfloat162*)(pWh + W_IN), (__nv_bfloat162*)(pWl + W_IN));
    split_kernel<<<(4 * Hn * Hn / 4) / 256, 256>>>((const float4*)Wih0,
        (__nv_bfloat162*)(pWh + W_IH0), (__nv_bfloat162*)(pWl + W_IH0));
    split_kernel<<<(4 * Hn * Hn / 4) / 256, 256>>>((const float4*)Wih1,
        (__nv_bfloat162*)(pWh + W_IH1), (__nv_bfloat162*)(pWl + W_IH1));
    split_kernel<<<(Fn * Hn / 4) / 256, 256>>>((const float4*)tahW,
        (__nv_bfloat162*)(pWh + W_TAH), (__nv_bfloat162*)(pWl + W_TAH));
    split_kernel<<<(Fn * Fn / 4) / 256, 256>>>((const float4*)taW,
        (__nv_bfloat162*)(pWh + W_TA), (__nv_bfloat162*)(pWl + W_TA));

    // 2) SA logits: sigmoid(xb @ saW^T + b) -> F2 fp32
    gemm_bf16_kernel<<<dim3(1, BT / 128), 256, bf16_smem>>>(
        pAh, pAl, pWh + W_SA, pWl + W_SA, sab, nullptr, pF2, nullptr, nullptr, Fn, Fn, 1);

    // 3) softmax + scale -> xs pair A2
    sa_softmax_kernel<<<BT, 128>>>(pF1, pF2, pBh, pBl);

    // 4) layer_in: xs @ inW^T + inb -> h_in pair A1
    gemm_bf16_kernel<<<dim3(2, BT / 128), 256, bf16_smem>>>(
        pBh, pBl, pWh + W_IN, pWl + W_IN, inb, nullptr, nullptr, pAh, pAl, Hn, Fn, 0);

    // 5) LSTM layer 0: gate GEMM -> G, persistent recurrence -> hall pair A2
    gemm_bf16_kernel<<<dim3(8, BT / 128), 256, bf16_smem>>>(
        pAh, pAl, pWh + W_IH0, pWl + W_IH0, bih0, bhh0, pG, nullptr, nullptr, 4 * Hn, Hn, 0);
    cudaMemsetAsync(pBar, 0, sizeof(unsigned));
    lstm_persist_kernel<<<dim3(16, 8), 256, lstm_smem>>>(pG, Whh0, pHh, pHl, pBh, pBl, 128u);

    // 6) LSTM layer 1 -> hall pair A1
    gemm_bf16_kernel<<<dim3(8, BT / 128), 256, bf16_smem>>>(
        pBh, pBl, pWh + W_IH1, pWl + W_IH1, bih1, bhh1, pG, nullptr, nullptr, 4 * Hn, Hn, 0);
    cudaMemsetAsync(pBar, 0, sizeof(unsigned));
    lstm_persist_kernel<<<dim3(16, 8), 256, lstm_smem>>>(pG, Whh1, pHh, pHl, pAh, pAl, 128u);

    // 7) temporal attention: total -> F1 fp32 + pair A2; relu logits -> F2
    gemm_bf16_kernel<<<dim3(1, BT / 128), 256, bf16_smem>>>(
        pAh, pAl, pWh + W_TAH, pWl + W_TAH, tahb, nullptr, pF1, pBh, pBl, Fn, Hn, 0);
    gemm_bf16_kernel<<<dim3(1, BT / 128), 256, bf16_smem>>>(
        pBh, pBl, pWh + W_TA, pWl + W_TA, tab, nullptr, pF2, nullptr, nullptr, Fn, Fn, 2);
    ctx_kernel<<<(Bn * Fn) / 256, 256>>>(pF2, pF1, pCtx);

    // 8) output
    out_kernel<<<Bn, 128>>>(pCtx, outW, (float*)d_out);
}

// round 12
// speedup vs baseline: 2.6939x; 1.0833x over previous
#include <cuda_runtime.h>
#include <cuda_bf16.h>
#include <cstdint>

#define Bn 256
#define Tn 512
#define Fn 128
#define Hn 256
#define BT (Bn*Tn)
#define BH (Bn*Hn)
#define SROW 72
#define SROWK 264   // LSTM smem row stride (256 k + 8 pad)

// weight split buffer offsets (elements)
#define W_SA   0
#define W_IN   16384
#define W_IH0  49152
#define W_IH1  311296
#define W_TAH  573440
#define W_TA   606208
#define W_TOT  622592

// ---------------- scratch (device globals) ----------------
__device__ float g_bufF1[(size_t)BT * Fn];
__device__ float g_bufF2[(size_t)BT * Fn];
__device__ float g_bufG [(size_t)BT * 4 * Hn];
__device__ float g_ctxbuf[Bn * Fn];
__device__ unsigned g_bars[8 * 32];                 // per-b-group barrier counters (128B apart)
__device__ __nv_bfloat16 g_a16h[(size_t)BT * Hn];   // activation pair buffer A1
__device__ __nv_bfloat16 g_a16l[(size_t)BT * Hn];
__device__ __nv_bfloat16 g_b16h[(size_t)BT * Hn];   // activation pair buffer A2
__device__ __nv_bfloat16 g_b16l[(size_t)BT * Hn];
__device__ __nv_bfloat16 g_w16h[W_TOT];             // all weights hi
__device__ __nv_bfloat16 g_w16l[W_TOT];             // all weights lo
__device__ __nv_bfloat16 g_h16h[2 * BH];            // ping-pong h (bf16 hi)
__device__ __nv_bfloat16 g_h16l[2 * BH];            // ping-pong h (bf16 lo)

// ---------------- BatchNorm (eval) + bf16 pair emit ----------------
__global__ void bn_kernel(const float4* __restrict__ x, const float4* __restrict__ g,
                          const float4* __restrict__ bt, const float4* __restrict__ mn,
                          const float4* __restrict__ vr, float4* __restrict__ out,
                          __nv_bfloat162* __restrict__ oh, __nv_bfloat162* __restrict__ ol)
{
    int i = blockIdx.x * 256 + threadIdx.x;
    int fi = i & 31;
    float4 xv = x[i];
    float4 gv = g[fi];
    float4 bv = bt[fi];
    float4 mv = mn[fi];
    float4 vv = vr[fi];
    float4 r;
    r.x = (xv.x - mv.x) * rsqrtf(vv.x + 1e-5f) * gv.x + bv.x;
    r.y = (xv.y - mv.y) * rsqrtf(vv.y + 1e-5f) * gv.y + bv.y;
    r.z = (xv.z - mv.z) * rsqrtf(vv.z + 1e-5f) * gv.z + bv.z;
    r.w = (xv.w - mv.w) * rsqrtf(vv.w + 1e-5f) * gv.w + bv.w;
    out[i] = r;
    __nv_bfloat162 h0 = __floats2bfloat162_rn(r.x, r.y);
    __nv_bfloat162 h1 = __floats2bfloat162_rn(r.z, r.w);
    float lx = r.x - __bfloat162float(__low2bfloat16(h0));
    float ly = r.y - __bfloat162float(__high2bfloat16(h0));
    float lz = r.z - __bfloat162float(__low2bfloat16(h1));
    float lw = r.w - __bfloat162float(__high2bfloat16(h1));
    oh[2 * i]     = h0;
    oh[2 * i + 1] = h1;
    ol[2 * i]     = __floats2bfloat162_rn(lx, ly);
    ol[2 * i + 1] = __floats2bfloat162_rn(lz, lw);
}

// ---------------- fp32 -> bf16 hi/lo split (weights) ----------------
__global__ void split_kernel(const float4* __restrict__ x,
                             __nv_bfloat162* __restrict__ hh,
                             __nv_bfloat162* __restrict__ ll)
{
    int i = blockIdx.x * 256 + threadIdx.x;
    float4 v = x[i];
    __nv_bfloat162 h0 = __floats2bfloat162_rn(v.x, v.y);
    __nv_bfloat162 h1 = __floats2bfloat162_rn(v.z, v.w);
    float lx = v.x - __bfloat162float(__low2bfloat16(h0));
    float ly = v.y - __bfloat162float(__high2bfloat16(h0));
    float lz = v.z - __bfloat162float(__low2bfloat16(h1));
    float lw = v.w - __bfloat162float(__high2bfloat16(h1));
    hh[2 * i]     = h0;
    hh[2 * i + 1] = h1;
    ll[2 * i]     = __floats2bfloat162_rn(lx, ly);
    ll[2 * i + 1] = __floats2bfloat162_rn(lz, lw);
}

// ---------------- tensor-core helpers ----------------
__device__ __forceinline__ void ldsm_x4(uint32_t* r, uint32_t saddr)
{
    asm volatile("ldmatrix.sync.aligned.m8n8.x4.shared.b16 {%0,%1,%2,%3}, [%4];"
                 : "=r"(r[0]), "=r"(r[1]), "=r"(r[2]), "=r"(r[3]) : "r"(saddr));
}

__device__ __forceinline__ void ldsm_x2(uint32_t* r, uint32_t saddr)
{
    asm volatile("ldmatrix.sync.aligned.m8n8.x2.shared.b16 {%0,%1}, [%2];"
                 : "=r"(r[0]), "=r"(r[1]) : "r"(saddr));
}

__device__ __forceinline__ void mma_bf16(float* d, const uint32_t* a, const uint32_t* b)
{
    asm volatile("mma.sync.aligned.m16n8k16.row.col.f32.bf16.bf16.f32 "
                 "{%0,%1,%2,%3}, {%4,%5,%6,%7}, {%8,%9}, {%0,%1,%2,%3};"
                 : "+f"(d[0]), "+f"(d[1]), "+f"(d[2]), "+f"(d[3])
                 : "r"(a[0]), "r"(a[1]), "r"(a[2]), "r"(a[3]), "r"(b[0]), "r"(b[1]));
}

// ---------------- unified bf16-split tensor GEMM ----------------
__global__ __launch_bounds__(256) void gemm_bf16_kernel(
    const __nv_bfloat16* __restrict__ Ahg, const __nv_bfloat16* __restrict__ Alg,
    const __nv_bfloat16* __restrict__ Whg, const __nv_bfloat16* __restrict__ Wlg,
    const float* __restrict__ b1, const float* __restrict__ b2,
    float* __restrict__ Cf, __nv_bfloat16* __restrict__ Chi, __nv_bfloat16* __restrict__ Clo,
    int N, int K, int epi)
{
    extern __shared__ char dynsmem[];
    __nv_bfloat16* sAh = (__nv_bfloat16*)dynsmem;
    __nv_bfloat16* sAl = sAh + 128 * SROW;
    __nv_bfloat16* sWh = sAl + 128 * SROW;
    __nv_bfloat16* sWl = sWh + 128 * SROW;

    const int m0 = blockIdx.y << 7;
    const int n0 = blockIdx.x << 7;
    const int tid = (int)threadIdx.x;
    const int wid = tid >> 5;
    const int lane = tid & 31;
    const int wm0 = (wid >> 2) << 6;
    const int wn0 = (wid & 3) << 5;

    const int arow = (lane & 7) + (((lane >> 3) & 1) << 3);
    const int acol = (lane >> 4) << 3;
    const int brow = (lane & 7) + ((lane >> 4) << 3);
    const int bcol = ((lane >> 3) & 1) << 3;

    const uint32_t sAh0 = (uint32_t)__cvta_generic_to_shared(sAh) + (uint32_t)(((wm0 + arow) * SROW + acol) * 2);
    const uint32_t sAl0 = (uint32_t)__cvta_generic_to_shared(sAl) + (uint32_t)(((wm0 + arow) * SROW + acol) * 2);
    const uint32_t sWh0 = (uint32_t)__cvta_generic_to_shared(sWh) + (uint32_t)(((wn0 + brow) * SROW + bcol) * 2);
    const uint32_t sWl0 = (uint32_t)__cvta_generic_to_shared(sWl) + (uint32_t)(((wn0 + brow) * SROW + bcol) * 2);

    float acc[16][4];
#pragma unroll
    for (int i = 0; i < 16; i++) {
#pragma unroll
        for (int j = 0; j < 4; j++) { acc[i][j] = 0.f; }
    }

    const int lr = tid >> 1;
    const int lc = (tid & 1) << 5;
    const int nkc = K >> 6;

    for (int kc = 0; kc < nkc; kc++) {
        const __nv_bfloat16* ag = Ahg + (size_t)(m0 + lr) * K + kc * 64 + lc;
        const __nv_bfloat16* al = Alg + (size_t)(m0 + lr) * K + kc * 64 + lc;
        const __nv_bfloat16* wg = Whg + (size_t)(n0 + lr) * K + kc * 64 + lc;
        const __nv_bfloat16* wl = Wlg + (size_t)(n0 + lr) * K + kc * 64 + lc;
        __nv_bfloat16* dA_h = sAh + lr * SROW + lc;
        __nv_bfloat16* dA_l = sAl + lr * SROW + lc;
        __nv_bfloat16* dW_h = sWh + lr * SROW + lc;
        __nv_bfloat16* dW_l = sWl + lr * SROW + lc;
#pragma unroll
        for (int q = 0; q < 4; q++) {
            ((uint4*)(dA_h + q * 8))[0] = ((const uint4*)(ag + q * 8))[0];
            ((uint4*)(dA_l + q * 8))[0] = ((const uint4*)(al + q * 8))[0];
            ((uint4*)(dW_h + q * 8))[0] = ((const uint4*)(wg + q * 8))[0];
            ((uint4*)(dW_l + q * 8))[0] = ((const uint4*)(wl + q * 8))[0];
        }
        __syncthreads();

#pragma unroll
        for (int ks = 0; ks < 4; ks++) {
            const uint32_t koff = (uint32_t)(ks * 32);
            uint32_t afr[4][4];
            uint32_t bh[4][2];
            uint32_t bl[4][2];
#pragma unroll
            for (int fp = 0; fp < 2; fp++) {
                uint32_t tmp[4];
                ldsm_x4(tmp, sWh0 + (uint32_t)(fp * 16 * SROW * 2) + koff);
                bh[2 * fp][0] = tmp[0];
                bh[2 * fp][1] = tmp[1];
                bh[2 * fp + 1][0] = tmp[2];
                bh[2 * fp + 1][1] = tmp[3];
                ldsm_x4(tmp, sWl0 + (uint32_t)(fp * 16 * SROW * 2) + koff);
                bl[2 * fp][0] = tmp[0];
                bl[2 * fp][1] = tmp[1];
                bl[2 * fp + 1][0] = tmp[2];
                bl[2 * fp + 1][1] = tmp[3];
            }
#pragma unroll
            for (int fm = 0; fm < 4; fm++) {
                ldsm_x4(afr[fm], sAh0 + (uint32_t)(fm * 16 * SROW * 2) + koff);
            }
#pragma unroll
            for (int fm = 0; fm < 4; fm++) {
#pragma unroll
                for (int fn = 0; fn < 4; fn++) {
                    mma_bf16(acc[fm * 4 + fn], afr[fm], bh[fn]);
                    mma_bf16(acc[fm * 4 + fn], afr[fm], bl[fn]);
                }
            }
#pragma unroll
            for (int fm = 0; fm < 4; fm++) {
                ldsm_x4(afr[fm], sAl0 + (uint32_t)(fm * 16 * SROW * 2) + koff);
            }
#pragma unroll
            for (int fm = 0; fm < 4; fm++) {
#pragma unroll
                for (int fn = 0; fn < 4; fn++) {
                    mma_bf16(acc[fm * 4 + fn], afr[fm], bh[fn]);
                }
            }
        }
        __syncthreads();
    }

#pragma unroll
    for (int fm = 0; fm < 4; fm++) {
#pragma unroll
        for (int fn = 0; fn < 4; fn++) {
            float* d = acc[fm * 4 + fn];
            int row = m0 + wm0 + fm * 16 + (lane >> 2);
            int col = n0 + wn0 + fn * 8 + ((lane & 3) << 1);
            float bv0 = b1[col];
            float bv1 = b1[col + 1];
            if (b2 != nullptr) {
                bv0 += b2[col];
                bv1 += b2[col + 1];
            }
            float v00 = d[0] + bv0;
            float v01 = d[1] + bv1;
            float v10 = d[2] + bv0;
            float v11 = d[3] + bv1;
            if (epi == 1) {
                v00 = 1.f / (1.f + expf(-v00));
                v01 = 1.f / (1.f + expf(-v01));
                v10 = 1.f / (1.f + expf(-v10));
                v11 = 1.f / (1.f + expf(-v11));
            } else if (epi == 2) {
                v00 = fmaxf(v00, 0.f);
                v01 = fmaxf(v01, 0.f);
                v10 = fmaxf(v10, 0.f);
                v11 = fmaxf(v11, 0.f);
            }
            if (Cf != nullptr) {
                ((float2*)(Cf + (size_t)row * N + col))[0]       = make_float2(v00, v01);
                ((float2*)(Cf + (size_t)(row + 8) * N + col))[0] = make_float2(v10, v11);
            }
            if (Chi != nullptr) {
                __nv_bfloat162 h0 = __floats2bfloat162_rn(v00, v01);
                __nv_bfloat162 h1 = __floats2bfloat162_rn(v10, v11);
                float l00 = v00 - __bfloat162float(__low2bfloat16(h0));
                float l01 = v01 - __bfloat162float(__high2bfloat16(h0));
                float l10 = v10 - __bfloat162float(__low2bfloat16(h1));
                float l11 = v11 - __bfloat162float(__high2bfloat16(h1));
                ((__nv_bfloat162*)(Chi + (size_t)row * N + col))[0]       = h0;
                ((__nv_bfloat162*)(Chi + (size_t)(row + 8) * N + col))[0] = h1;
                ((__nv_bfloat162*)(Clo + (size_t)row * N + col))[0]       = __floats2bfloat162_rn(l00, l01);
                ((__nv_bfloat162*)(Clo + (size_t)(row + 8) * N + col))[0] = __floats2bfloat162_rn(l10, l11);
            }
        }
    }
}

// ---------------- spatial-attention softmax + scale, emits xs as bf16 pair ----------------
__global__ void sa_softmax_kernel(const float* __restrict__ xb, const float* __restrict__ sx,
                                  __nv_bfloat16* __restrict__ oh, __nv_bfloat16* __restrict__ ol)
{
    int row = blockIdx.x;
    int f = threadIdx.x;
    size_t idx = ((size_t)row << 7) + f;
    float e = expf(sx[idx]);
    float sum = e;
#pragma unroll
    for (int o = 16; o > 0; o >>= 1) { sum += __shfl_xor_sync(0xffffffffu, sum, o); }
    __shared__ float red[4];
    if ((f & 31) == 0) { red[f >> 5] = sum; }
    __syncthreads();
    float tot = red[0] + red[1] + red[2] + red[3];
    float v = xb[idx] * e / tot;
    __nv_bfloat16 hi = __float2bfloat16(v);
    __nv_bfloat16 lo = __float2bfloat16(v - __bfloat162float(hi));
    oh[idx] = hi;
    ol[idx] = lo;
}

// ---------------- persistent LSTM layer (tensor-core recurrent GEMM) ----------------
// 128 blocks = (16 u-tiles x 8 b-groups), 256 threads. Synchronization is PER B-GROUP:
// block (ux, by) writes h rows [by*32, by*32+32) and reads only those same rows, so only
// the 16 blocks sharing `by` must sync each step (8 independent counters, 128B apart).
__global__ __launch_bounds__(256) void lstm_persist_kernel(
    const float* __restrict__ G, const float* __restrict__ Whh,
    __nv_bfloat16* __restrict__ h16h, __nv_bfloat16* __restrict__ h16l,
    __nv_bfloat16* __restrict__ hallh, __nv_bfloat16* __restrict__ halll)
{
    extern __shared__ char dynsmem[];
    __nv_bfloat16* wsh = (__nv_bfloat16*)dynsmem;
    __nv_bfloat16* wsl = wsh + 64 * SROWK;
    __nv_bfloat16* hsh = wsl + 64 * SROWK;
    __nv_bfloat16* hsl = hsh + 32 * SROWK;
    float* Ssm = (float*)(hsl + 32 * SROWK);
    float* csm = Ssm + 32 * 68;

    const int u0 = blockIdx.x << 4;
    const int b0 = blockIdx.y << 5;
    const int tid = (int)threadIdx.x;
    const int wid = tid >> 5;
    const int lane = tid & 31;
    unsigned* bar = &g_bars[blockIdx.y << 5];   // this b-group's counter (128B-separated)

#pragma unroll 4
    for (int i = 0; i < 16; i++) {
        int f4 = tid + (i << 8);
        int c  = f4 >> 6;
        int kq = (f4 & 63) << 2;
        int wrow = ((c >> 4) << 8) + u0 + (c & 15);
        float4 v = ((const float4*)(Whh + (size_t)wrow * Hn + kq))[0];
        __nv_bfloat162 h0 = __floats2bfloat162_rn(v.x, v.y);
        __nv_bfloat162 h1 = __floats2bfloat162_rn(v.z, v.w);
        float lx = v.x - __bfloat162float(__low2bfloat16(h0));
        float ly = v.y - __bfloat162float(__high2bfloat16(h0));
        float lz = v.z - __bfloat162float(__low2bfloat16(h1));
        float lw = v.w - __bfloat162float(__high2bfloat16(h1));
        ((__nv_bfloat162*)(wsh + c * SROWK + kq))[0] = h0;
        ((__nv_bfloat162*)(wsh + c * SROWK + kq))[1] = h1;
        ((__nv_bfloat162*)(wsl + c * SROWK + kq))[0] = __floats2bfloat162_rn(lx, ly);
        ((__nv_bfloat162*)(wsl + c * SROWK + kq))[1] = __floats2bfloat162_rn(lz, lw);
    }
    for (int i = tid; i < 32 * 18; i += 256) { csm[i] = 0.f; }
    __syncthreads();

    const int lane15 = lane & 15;
    const uint32_t aBaseH = (uint32_t)__cvta_generic_to_shared(hsh)
                          + (uint32_t)((lane15 * SROWK + ((lane >> 4) << 3)) * 2);
    const uint32_t aBaseL = (uint32_t)__cvta_generic_to_shared(hsl)
                          + (uint32_t)((lane15 * SROWK + ((lane >> 4) << 3)) * 2);
    const uint32_t bBaseH = (uint32_t)__cvta_generic_to_shared(wsh)
                          + (uint32_t)((((wid << 3) + (lane15 & 7)) * SROWK + (((lane15 >> 3) & 1) << 3)) * 2);
    const uint32_t bBaseL = (uint32_t)__cvta_generic_to_shared(wsl)
                          + (uint32_t)((((wid << 3) + (lane15 & 7)) * SROWK + (((lane15 >> 3) & 1) << 3)) * 2);

    const int uu = (tid << 1) & 15;
    const int bb = tid >> 3;
    const int gb = b0 + bb;
    const int gu = u0 + uu;

    unsigned target = 0;
    for (int t = 0; t < Tn; t++) {
        float2 gqi, gqf, gqg, gqo;
        {
            const float* gp = G + (((size_t)gb * Tn + t) << 10) + gu;
            gqi = ((const float2*)(gp +   0))[0];
            gqf = ((const float2*)(gp + 256))[0];
            gqg = ((const float2*)(gp + 512))[0];
            gqo = ((const float2*)(gp + 768))[0];
        }

        float acc0[4];
        float acc1[4];
#pragma unroll
        for (int j = 0; j < 4; j++) { acc0[j] = 0.f; acc1[j] = 0.f; }

        if (t > 0) {
            const __nv_bfloat16* hph = h16h + (size_t)(t & 1) * BH;
            const __nv_bfloat16* hpl = h16l + (size_t)(t & 1) * BH;
#pragma unroll 4
            for (int i = 0; i < 4; i++) {
                int f4 = tid + (i << 8);
                int hbb = f4 >> 5;
                int k8 = (f4 & 31) << 3;
                uint4 vh = __ldcg((const uint4*)(hph + (size_t)(b0 + hbb) * Hn + k8));
                uint4 vl = __ldcg((const uint4*)(hpl + (size_t)(b0 + hbb) * Hn + k8));
                ((uint4*)(hsh + hbb * SROWK + k8))[0] = vh;
                ((uint4*)(hsl + hbb * SROWK + k8))[0] = vl;
            }
            __syncthreads();

#pragma unroll
            for (int ks = 0; ks < 16; ks++) {
                const uint32_t koff = (uint32_t)(ks * 32);
                uint32_t bh[2];
                uint32_t bl[2];
                uint32_t a0[4];
                uint32_t a1[4];
                ldsm_x2(bh, bBaseH + koff);
                ldsm_x2(bl, bBaseL + koff);
                ldsm_x4(a0, aBaseH + koff);
                ldsm_x4(a1, aBaseH + (uint32_t)(16 * SROWK * 2) + koff);
                mma_bf16(acc0, a0, bh);
                mma_bf16(acc1, a1, bh);
                mma_bf16(acc0, a0, bl);
                mma_bf16(acc1, a1, bl);
                ldsm_x4(a0, aBaseL + koff);
                ldsm_x4(a1, aBaseL + (uint32_t)(16 * SROWK * 2) + koff);
                mma_bf16(acc0, a0, bh);
                mma_bf16(acc1, a1, bh);
            }
            // NOTE: no __syncthreads here — hsh/hsl are not rewritten until after the
            // group barrier below, whose trailing __syncthreads orders all MMA reads.
        }

        {
            int r0 = lane >> 2;
            int cb = (wid << 3) + ((lane & 3) << 1);
            Ssm[(r0 +  0) * 68 + cb]     = acc0[0];
            Ssm[(r0 +  0) * 68 + cb + 1] = acc0[1];
            Ssm[(r0 +  8) * 68 + cb]     = acc0[2];
            Ssm[(r0 +  8) * 68 + cb + 1] = acc0[3];
            Ssm[(r0 + 16) * 68 + cb]     = acc1[0];
            Ssm[(r0 + 16) * 68 + cb + 1] = acc1[1];
            Ssm[(r0 + 24) * 68 + cb]     = acc1[2];
            Ssm[(r0 + 24) * 68 + cb + 1] = acc1[3];
        }
        __syncthreads();

        {
            const float* S0 = Ssm + bb * 68;
            float hv[2];
            float cn[2];
            float2 cpv = ((const float2*)&csm[bb * 18 + uu])[0];
            float cprev[2] = {cpv.x, cpv.y};
            float gi2[2] = {gqi.x, gqi.y};
            float gf2[2] = {gqf.x, gqf.y};
            float gg2[2] = {gqg.x, gqg.y};
            float go2[2] = {gqo.x, gqo.y};
#pragma unroll
            for (int e = 0; e < 2; e++) {
                int ue = uu + e;
                float gi = gi2[e] + S0[ 0 + ue];
                float gf = gf2[e] + S0[16 + ue];
                float gg = gg2[e] + S0[32 + ue];
                float go = go2[e] + S0[48 + ue];
                float si = 1.f / (1.f + expf(-gi));
                float sf = 1.f / (1.f + expf(-gf));
                float so = 1.f / (1.f + expf(-go));
                float tg = tanhf(gg);
                cn[e] = sf * cprev[e] + si * tg;
                hv[e] = so * tanhf(cn[e]);
            }
            ((float2*)&csm[bb * 18 + uu])[0] = make_float2(cn[0], cn[1]);
            __nv_bfloat162 hh = __floats2bfloat162_rn(hv[0], hv[1]);
            float l0 = hv[0] - __bfloat162float(__low2bfloat16(hh));
            float l1 = hv[1] - __bfloat162float(__high2bfloat16(hh));
            __nv_bfloat162 hl = __floats2bfloat162_rn(l0, l1);
            size_t hoff = (size_t)((t + 1) & 1) * BH + (size_t)gb * Hn + gu;
            ((__nv_bfloat162*)(h16h + hoff))[0] = hh;
            ((__nv_bfloat162*)(h16l + hoff))[0] = hl;
            size_t aoff = ((size_t)gb * Tn + t) * Hn + gu;
            ((__nv_bfloat162*)(hallh + aoff))[0] = hh;
            ((__nv_bfloat162*)(halll + aoff))[0] = hl;
        }

        // per-b-group barrier: only the 16 blocks sharing blockIdx.y must agree
        __syncthreads();
        __threadfence();
        target += 16u;
        if (tid == 0) {
            atomicAdd(bar, 1u);
            while (*((volatile unsigned*)bar) < target) { }
        }
        __syncthreads();
    }
}

// ---------------- temporal attention ----------------
__global__ void ctx_kernel(const float* __restrict__ blg, const float* __restrict__ tot,
                           float* __restrict__ ctx)
{
    int gid = blockIdx.x * 256 + threadIdx.x;
    int b = gid >> 7;
    int f = gid & 127;
    const float* lp = blg + (((size_t)b * Tn) << 7) + f;
    const float* tp = tot + (((size_t)b * Tn) << 7) + f;
    float m = -1e30f;
    for (int t = 0; t < Tn; t++) { m = fmaxf(m, lp[(size_t)t << 7]); }
    float s = 0.f;
    float w = 0.f;
    for (int t = 0; t < Tn; t++) {
        float e = expf(lp[(size_t)t << 7] - m);
        s += e;
        w = fmaf(e, tp[(size_t)t << 7], w);
    }
    ctx[gid] = w / s;
}

// ---------------- final projection ----------------
__global__ void out_kernel(const float* __restrict__ ctx, const float* __restrict__ ow,
                           float* __restrict__ out)
{
    int b = blockIdx.x;
    int f = threadIdx.x;
    float v = ctx[(b << 7) + f] * ow[f];
#pragma unroll
    for (int o = 16; o > 0; o >>= 1) { v += __shfl_xor_sync(0xffffffffu, v, o); }
    __shared__ float red[4];
    if ((f & 31) == 0) { red[f >> 5] = v; }
    __syncthreads();
    if (f == 0) { out[b] = red[0] + red[1] + red[2] + red[3]; }
}

// ---------------- host ----------------
extern "C" void kernel_launch(void* const* d_in, const int* in_sizes, int n_in,
                              void* d_out, int out_size)
{
    (void)in_sizes; (void)n_in; (void)out_size;
    const float* x    = (const float*)d_in[0];
    const float* bng  = (const float*)d_in[1];
    const float* bnb  = (const float*)d_in[2];
    const float* bnm  = (const float*)d_in[3];
    const float* bnv  = (const float*)d_in[4];
    const float* saW  = (const float*)d_in[5];
    const float* sab  = (const float*)d_in[6];
    const float* inW  = (const float*)d_in[7];
    const float* inb  = (const float*)d_in[8];
    const float* Wih0 = (const float*)d_in[9];
    const float* Whh0 = (const float*)d_in[10];
    const float* bih0 = (const float*)d_in[11];
    const float* bhh0 = (const float*)d_in[12];
    const float* Wih1 = (const float*)d_in[13];
    const float* Whh1 = (const float*)d_in[14];
    const float* bih1 = (const float*)d_in[15];
    const float* bhh1 = (const float*)d_in[16];
    const float* tahW = (const float*)d_in[17];
    const float* tahb = (const float*)d_in[18];
    const float* taW  = (const float*)d_in[19];
    const float* tab  = (const float*)d_in[20];
    const float* outW = (const float*)d_in[21];

    float *pF1, *pF2, *pG, *pCtx;
    unsigned* pBar;
    __nv_bfloat16 *pAh, *pAl, *pBh, *pBl, *pWh, *pWl, *pHh, *pHl;
    cudaGetSymbolAddress((void**)&pF1, g_bufF1);
    cudaGetSymbolAddress((void**)&pF2, g_bufF2);
    cudaGetSymbolAddress((void**)&pG,  g_bufG);
    cudaGetSymbolAddress((void**)&pCtx, g_ctxbuf);
    cudaGetSymbolAddress((void**)&pBar, g_bars);
    cudaGetSymbolAddress((void**)&pAh, g_a16h);
    cudaGetSymbolAddress((void**)&pAl, g_a16l);
    cudaGetSymbolAddress((void**)&pBh, g_b16h);
    cudaGetSymbolAddress((void**)&pBl, g_b16l);
    cudaGetSymbolAddress((void**)&pWh, g_w16h);
    cudaGetSymbolAddress((void**)&pWl, g_w16l);
    cudaGetSymbolAddress((void**)&pHh, g_h16h);
    cudaGetSymbolAddress((void**)&pHl, g_h16l);

    const int lstm_smem = (64 * SROWK + 64 * SROWK + 32 * SROWK + 32 * SROWK) * 2
                        + (32 * 68 + 32 * 18) * 4;
    cudaFuncSetAttribute(lstm_persist_kernel,
                         cudaFuncAttributeMaxDynamicSharedMemorySize, lstm_smem);
    const int bf16_smem = 4 * 128 * SROW * 2;
    cudaFuncSetAttribute(gemm_bf16_kernel,
                         cudaFuncAttributeMaxDynamicSharedMemorySize, bf16_smem);

    // 1) BN: xb -> F1 fp32 + pair A1
    bn_kernel<<<(BT * Fn / 4) / 256, 256>>>((const float4*)x, (const float4*)bng,
        (const float4*)bnb, (const float4*)bnm, (const float4*)bnv, (float4*)pF1,
        (__nv_bfloat162*)pAh, (__nv_bfloat162*)pAl);

    // weight splits
    split_kernel<<<(Fn * Fn / 4) / 256, 256>>>((const float4*)saW,
        (__nv_bfloat162*)(pWh + W_SA), (__nv_bfloat162*)(pWl + W_SA));
    split_kernel<<<(Hn * Fn / 4) / 256, 256>>>((const float4*)inW,
        (__nv_bfloat162*)(pWh + W_IN), (__nv_bfloat162*)(pWl + W_IN));
    split_kernel<<<(4 * Hn * Hn / 4) / 256, 256>>>((const float4*)Wih0,
        (__nv_bfloat162*)(pWh + W_IH0), (__nv_bfloat162*)(pWl + W_IH0));
    split_kernel<<<(4 * Hn * Hn / 4) / 256, 256>>>((const float4*)Wih1,
        (__nv_bfloat162*)(pWh + W_IH1), (__nv_bfloat162*)(pWl + W_IH1));
    split_kernel<<<(Fn * Hn / 4) / 256, 256>>>((const float4*)tahW,
        (__nv_bfloat162*)(pWh + W_TAH), (__nv_bfloat162*)(pWl + W_TAH));
    split_kernel<<<(Fn * Fn / 4) / 256, 256>>>((const float4*)taW,
        (__nv_bfloat162*)(pWh + W_TA), (__nv_bfloat162*)(pWl + W_TA));

    // 2) SA logits
    gemm_bf16_kernel<<<dim3(1, BT / 128), 256, bf16_smem>>>(
        pAh, pAl, pWh + W_SA, pWl + W_SA, sab, nullptr, pF2, nullptr, nullptr, Fn, Fn, 1);

    // 3) softmax + scale -> xs pair A2
    sa_softmax_kernel<<<BT, 128>>>(pF1, pF2, pBh, pBl);

    // 4) layer_in -> h_in pair A1
    gemm_bf16_kernel<<<dim3(2, BT / 128), 256, bf16_smem>>>(
        pBh, pBl, pWh + W_IN, pWl + W_IN, inb, nullptr, nullptr, pAh, pAl, Hn, Fn, 0);

    // 5) LSTM layer 0
    gemm_bf16_kernel<<<dim3(8, BT / 128), 256, bf16_smem>>>(
        pAh, pAl, pWh + W_IH0, pWl + W_IH0, bih0, bhh0, pG, nullptr, nullptr, 4 * Hn, Hn, 0);
    cudaMemsetAsync(pBar, 0, 8 * 32 * sizeof(unsigned));
    lstm_persist_kernel<<<dim3(16, 8), 256, lstm_smem>>>(pG, Whh0, pHh, pHl, pBh, pBl);

    // 6) LSTM layer 1
    gemm_bf16_kernel<<<dim3(8, BT / 128), 256, bf16_smem>>>(
        pBh, pBl, pWh + W_IH1, pWl + W_IH1, bih1, bhh1, pG, nullptr, nullptr, 4 * Hn, Hn, 0);
    cudaMemsetAsync(pBar, 0, 8 * 32 * sizeof(unsigned));
    lstm_persist_kernel<<<dim3(16, 8), 256, lstm_smem>>>(pG, Whh1, pHh, pHl, pAh, pAl);

    // 7) temporal attention
    gemm_bf16_kernel<<<dim3(1, BT / 128), 256, bf16_smem>>>(
        pAh, pAl, pWh + W_TAH, pWl + W_TAH, tahb, nullptr, pF1, pBh, pBl, Fn, Hn, 0);
    gemm_bf16_kernel<<<dim3(1, BT / 128), 256, bf16_smem>>>(
        pBh, pBl, pWh + W_TA, pWl + W_TA, tab, nullptr, pF2, nullptr, nullptr, Fn, Fn, 2);
    ctx_kernel<<<(Bn * Fn) / 256, 256>>>(pF2, pF1, pCtx);

    // 8) output
    out_kernel<<<Bn, 128>>>(pCtx, outW, (float*)d_out);
}